// round 15
// baseline (speedup 1.0000x reference)
#include <cuda_runtime.h>
#include <cstdint>

#define NN 100000
#define EE 640000
#define GG 256
#define HH 128
#define TPB 256
#define BM 64
#define EBM 128
#define ETPB 512
#define LDA 132
#define LDB 136
#define LDAS 36
#define LDAP 20
#define LDBP 136

typedef long long ll;

// ---------------- scratch ----------------
__device__ float g_h[NN * HH];
__device__ float g_agg[NN * HH];
__device__ float g_p1[NN * HH];
__device__ float g_p2[NN * HH];
__device__ uint32_t g_e[(ll)EE * HH];     // e stored as tf32 bit patterns
__device__ float g_deg[NN];
__device__ float g_pool[GG * HH];
__device__ float g_cnt[GG];

// pre-converted weights
__device__ uint32_t g_wu_h[3 * 128 * HH],   g_wu_l[3 * 128 * HH];
__device__ uint32_t g_wn_h[3 * 64 * HH],    g_wn_l[3 * 64 * HH];
__device__ uint32_t g_wm12_h[3 * 128 * HH], g_wm12_l[3 * 128 * HH];
__device__ uint32_t g_wm3_t[3 * 128 * HH];
__device__ uint32_t g_we_t[3 * 128 * HH];
__device__ uint32_t g_we0_t[16 * HH];

// ---------------- helpers ----------------
__device__ __forceinline__ uint32_t f2tf(float f) {
    uint32_t u;
    asm("cvt.rna.tf32.f32 %0, %1;" : "=r"(u) : "f"(f));
    return u;
}
__device__ __forceinline__ void mma_tf32(float* c, uint32_t a0, uint32_t a1,
                                         uint32_t a2, uint32_t a3,
                                         uint32_t b0, uint32_t b1) {
    asm volatile(
        "mma.sync.aligned.m16n8k8.row.col.f32.tf32.tf32.f32 "
        "{%0,%1,%2,%3}, {%4,%5,%6,%7}, {%8,%9}, {%0,%1,%2,%3};\n"
        : "+f"(c[0]), "+f"(c[1]), "+f"(c[2]), "+f"(c[3])
        : "r"(a0), "r"(a1), "r"(a2), "r"(a3), "r"(b0), "r"(b1));
}
__device__ __forceinline__ void split_pack(float v0, float v1,
                                           uint32_t& ph, uint32_t& pl) {
    uint32_t h;
    asm("cvt.rn.bf16x2.f32 %0, %1, %2;" : "=r"(h) : "f"(v1), "f"(v0));
    float h0 = __uint_as_float(h << 16);
    float h1 = __uint_as_float(h & 0xffff0000u);
    asm("cvt.rn.bf16x2.f32 %0, %1, %2;" : "=r"(pl) : "f"(v1 - h1), "f"(v0 - h0));
    ph = h;
}
__device__ __forceinline__ void mma_bf16(float* c, uint32_t a0, uint32_t a1,
                                         uint32_t a2, uint32_t a3,
                                         uint32_t b0, uint32_t b1) {
    asm volatile(
        "mma.sync.aligned.m16n8k16.row.col.f32.bf16.bf16.f32 "
        "{%0,%1,%2,%3}, {%4,%5,%6,%7}, {%8,%9}, {%0,%1,%2,%3};\n"
        : "+f"(c[0]), "+f"(c[1]), "+f"(c[2]), "+f"(c[3])
        : "r"(a0), "r"(a1), "r"(a2), "r"(a3), "r"(b0), "r"(b1));
}
__device__ __forceinline__ void cpa16(uint32_t* smem_dst, const void* gsrc) {
    uint32_t saddr = (uint32_t)__cvta_generic_to_shared(smem_dst);
    asm volatile("cp.async.cg.shared.global [%0], [%1], 16;\n"
                 :: "r"(saddr), "l"(gsrc));
}
#define CP_COMMIT() asm volatile("cp.async.commit_group;\n" ::: "memory")
#define CP_WAIT(n)  asm volatile("cp.async.wait_group %0;\n" :: "n"(n) : "memory")

// ---------------- weight prep + misc zero (one launch) ----------------
__global__ void k_prep(const float* __restrict__ WM, const float* __restrict__ WU,
                       const float* __restrict__ Wn, const float* __restrict__ We,
                       const float* __restrict__ We0) {
    int i = blockIdx.x * blockDim.x + threadIdx.x;
    if (i < 3 * 40960) {
        int l = i / 40960, j = i % 40960;
        const float* W;
        uint32_t *dh, *dl;
        if (j < 16384)      { W = WU + (ll)l * 256 * HH; dh = g_wu_h + l * 16384;  dl = g_wu_l + l * 16384; }
        else if (j < 24576) { j -= 16384; W = Wn + (ll)l * 128 * HH; dh = g_wn_h + l * 8192; dl = g_wn_l + l * 8192; }
        else                { j -= 24576; W = WM + (ll)l * 384 * HH; dh = g_wm12_h + l * 16384; dl = g_wm12_l + l * 16384; }
        int kp = j >> 7, n = j & 127;
        uint32_t h, lo;
        split_pack(W[(ll)(2 * kp) * HH + n], W[(ll)(2 * kp + 1) * HH + n], h, lo);
        dh[j] = h; dl[j] = lo;
    } else {
        int k = i - 3 * 40960;
        if (k < 3 * 16384) {
            int l = k / 16384, j = k % 16384;
            g_wm3_t[k] = f2tf(WM[(ll)l * 384 * HH + 256 * HH + j]);
        } else {
            k -= 3 * 16384;
            if (k < 3 * 16384) {
                g_we_t[k] = f2tf(We[k]);
            } else {
                k -= 3 * 16384;
                if (k < 16 * HH) {
                    g_we0_t[k] = f2tf(We0[k]);
                } else {
                    k -= 16 * HH;
                    if (k < NN) g_deg[k] = 0.f;
                    if (k < GG * HH) g_pool[k] = 0.f;
                    if (k < GG) g_cnt[k] = 0.f;
                }
            }
        }
    }
}

// ---------------- node-kernel smem partition (BM=64) ----------------
#define OFF_APH 0
#define OFF_APL (BM * LDAP)
#define OFF_B1H (2 * BM * LDAP)
#define OFF_B1L (OFF_B1H + 16 * LDBP)
#define OFF_B2H (OFF_B1H + 2 * 16 * LDBP)
#define OFF_B2L (OFF_B1H + 3 * 16 * LDBP)
#define OFF_CF  (OFF_B1H + 4 * 16 * LDBP)
#define NODE_SMEM ((OFF_CF + BM * LDA) * 4)

__device__ __forceinline__ void stage_Bpre(uint32_t* Bh, uint32_t* Bl,
                                           const uint32_t* __restrict__ GH,
                                           const uint32_t* __restrict__ GL, int kp0) {
    int t = threadIdx.x;
#pragma unroll
    for (int i = 0; i < 2; i++) {
        int f = t + i * TPB;
        int kp = f >> 5, n = (f & 31) << 2;
        *(uint4*)(Bh + kp * LDBP + n) = *(const uint4*)(GH + (ll)(kp0 + kp) * HH + n);
        *(uint4*)(Bl + kp * LDBP + n) = *(const uint4*)(GL + (ll)(kp0 + kp) * HH + n);
    }
}

__device__ __forceinline__ void stage_Abf(uint32_t* Ah, uint32_t* Al,
                                          int r, int q, float4 v0, float4 v1) {
    uint32_t h0, l0, h1, l1;
    split_pack(v0.x, v0.y, h0, l0);
    split_pack(v0.z, v0.w, h1, l1);
    *(uint2*)(Ah + r * LDAP + 2 * q) = make_uint2(h0, h1);
    *(uint2*)(Al + r * LDAP + 2 * q) = make_uint2(l0, l1);
    split_pack(v1.x, v1.y, h0, l0);
    split_pack(v1.z, v1.w, h1, l1);
    *(uint2*)(Ah + r * LDAP + 8 + 2 * q) = make_uint2(h0, h1);
    *(uint2*)(Al + r * LDAP + 8 + 2 * q) = make_uint2(l0, l1);
}

__device__ __forceinline__ void stage_Abf_fromCf(uint32_t* Ah, uint32_t* Al,
                                                 const float* Cf, int kc) {
    int t = threadIdx.x;
    int r = t >> 2, q = t & 3;
    float4 v0 = *(const float4*)(Cf + r * LDA + kc * 32 + q * 4);
    float4 v1 = *(const float4*)(Cf + r * LDA + kc * 32 + 16 + q * 4);
    stage_Abf(Ah, Al, r, q, v0, v1);
}

__device__ __forceinline__ void mma3_bf(const uint32_t* Ah, const uint32_t* Al,
                                        const uint32_t* Bh, const uint32_t* Bl,
                                        int wm, int wn, int lr, int ka,
                                        float acc[8][4]) {
#pragma unroll
    for (int ks = 0; ks < 2; ks++) {
        int kpb = ks * 8;
        uint32_t ah0 = Ah[(wm + lr) * LDAP + kpb + ka];
        uint32_t ah1 = Ah[(wm + 8 + lr) * LDAP + kpb + ka];
        uint32_t ah2 = Ah[(wm + lr) * LDAP + kpb + ka + 4];
        uint32_t ah3 = Ah[(wm + 8 + lr) * LDAP + kpb + ka + 4];
        uint32_t al0 = Al[(wm + lr) * LDAP + kpb + ka];
        uint32_t al1 = Al[(wm + 8 + lr) * LDAP + kpb + ka];
        uint32_t al2 = Al[(wm + lr) * LDAP + kpb + ka + 4];
        uint32_t al3 = Al[(wm + 8 + lr) * LDAP + kpb + ka + 4];
#pragma unroll
        for (int nt = 0; nt < 8; nt++) {
            int nb = wn + nt * 8 + lr;
            uint32_t bh0 = Bh[(kpb + ka) * LDBP + nb];
            uint32_t bh1 = Bh[(kpb + ka + 4) * LDBP + nb];
            uint32_t bl0 = Bl[(kpb + ka) * LDBP + nb];
            uint32_t bl1 = Bl[(kpb + ka + 4) * LDBP + nb];
            mma_bf16(acc[nt], ah0, ah1, ah2, ah3, bh0, bh1);
            mma_bf16(acc[nt], al0, al1, al2, al3, bh0, bh1);
            mma_bf16(acc[nt], ah0, ah1, ah2, ah3, bl0, bl1);
        }
    }
}

__device__ __forceinline__ void mma3_bf_dual(const uint32_t* Ah, const uint32_t* Al,
                                             const uint32_t* B1h, const uint32_t* B1l,
                                             const uint32_t* B2h, const uint32_t* B2l,
                                             int wm, int wn, int lr, int ka,
                                             float accA[8][4], float accB[8][4]) {
#pragma unroll
    for (int ks = 0; ks < 2; ks++) {
        int kpb = ks * 8;
        uint32_t ah0 = Ah[(wm + lr) * LDAP + kpb + ka];
        uint32_t ah1 = Ah[(wm + 8 + lr) * LDAP + kpb + ka];
        uint32_t ah2 = Ah[(wm + lr) * LDAP + kpb + ka + 4];
        uint32_t ah3 = Ah[(wm + 8 + lr) * LDAP + kpb + ka + 4];
        uint32_t al0 = Al[(wm + lr) * LDAP + kpb + ka];
        uint32_t al1 = Al[(wm + 8 + lr) * LDAP + kpb + ka];
        uint32_t al2 = Al[(wm + lr) * LDAP + kpb + ka + 4];
        uint32_t al3 = Al[(wm + 8 + lr) * LDAP + kpb + ka + 4];
#pragma unroll
        for (int nt = 0; nt < 8; nt++) {
            int nb = wn + nt * 8 + lr;
            uint32_t bh0 = B1h[(kpb + ka) * LDBP + nb];
            uint32_t bh1 = B1h[(kpb + ka + 4) * LDBP + nb];
            uint32_t bl0 = B1l[(kpb + ka) * LDBP + nb];
            uint32_t bl1 = B1l[(kpb + ka + 4) * LDBP + nb];
            mma_bf16(accA[nt], ah0, ah1, ah2, ah3, bh0, bh1);
            mma_bf16(accA[nt], al0, al1, al2, al3, bh0, bh1);
            mma_bf16(accA[nt], ah0, ah1, ah2, ah3, bl0, bl1);
            bh0 = B2h[(kpb + ka) * LDBP + nb];
            bh1 = B2h[(kpb + ka + 4) * LDBP + nb];
            bl0 = B2l[(kpb + ka) * LDBP + nb];
            bl1 = B2l[(kpb + ka + 4) * LDBP + nb];
            mma_bf16(accB[nt], ah0, ah1, ah2, ah3, bh0, bh1);
            mma_bf16(accB[nt], al0, al1, al2, al3, bh0, bh1);
            mma_bf16(accB[nt], ah0, ah1, ah2, ah3, bl0, bl1);
        }
    }
}

__device__ __forceinline__ void frag_relu_toCf(float* Cf, const float acc[8][4],
                                               const float* __restrict__ bias,
                                               int wm, int wn, int lr, int ka) {
#pragma unroll
    for (int nt = 0; nt < 8; nt++) {
        int col = wn + nt * 8 + (ka << 1);
        float2 bb = *(const float2*)(bias + col);
        Cf[(wm + lr) * LDA + col]         = fmaxf(acc[nt][0] + bb.x, 0.f);
        Cf[(wm + lr) * LDA + col + 1]     = fmaxf(acc[nt][1] + bb.y, 0.f);
        Cf[(wm + 8 + lr) * LDA + col]     = fmaxf(acc[nt][2] + bb.x, 0.f);
        Cf[(wm + 8 + lr) * LDA + col + 1] = fmaxf(acc[nt][3] + bb.y, 0.f);
    }
}

__device__ __forceinline__ void p_passes(uint32_t* Ah, uint32_t* Al,
                                         uint32_t* B1h, uint32_t* B1l,
                                         uint32_t* B2h, uint32_t* B2l, float* Cf,
                                         int layer,
                                         int n0, int wm, int wn, int lr, int ka) {
    const uint32_t* GH1 = g_wm12_h + layer * 128 * HH;
    const uint32_t* GL1 = g_wm12_l + layer * 128 * HH;
    const uint32_t* GH2 = GH1 + 64 * HH;
    const uint32_t* GL2 = GL1 + 64 * HH;
    float accA[8][4], accB[8][4];
#pragma unroll
    for (int i = 0; i < 8; i++)
#pragma unroll
        for (int j = 0; j < 4; j++) { accA[i][j] = 0.f; accB[i][j] = 0.f; }
#pragma unroll 1
    for (int kc = 0; kc < 4; kc++) {
        __syncthreads();
        stage_Abf_fromCf(Ah, Al, Cf, kc);
        stage_Bpre(B1h, B1l, GH1, GL1, kc * 16);
        stage_Bpre(B2h, B2l, GH2, GL2, kc * 16);
        __syncthreads();
        mma3_bf_dual(Ah, Al, B1h, B1l, B2h, B2l, wm, wn, lr, ka, accA, accB);
    }
    int row0 = n0 + wm + lr, row1 = row0 + 8;
#pragma unroll
    for (int nt = 0; nt < 8; nt++) {
        int col = wn + nt * 8 + (ka << 1);
        if (row0 < NN) {
            *(float2*)(g_p1 + (ll)row0 * HH + col) = make_float2(accA[nt][0], accA[nt][1]);
            *(float2*)(g_p2 + (ll)row0 * HH + col) = make_float2(accB[nt][0], accB[nt][1]);
        }
        if (row1 < NN) {
            *(float2*)(g_p1 + (ll)row1 * HH + col) = make_float2(accA[nt][2], accA[nt][3]);
            *(float2*)(g_p2 + (ll)row1 * HH + col) = make_float2(accB[nt][2], accB[nt][3]);
        }
    }
}

// ---------------- fp32 helpers (node encoder) ----------------
template<int KC>
__device__ __forceinline__ void load_B(float* Bs, const float* __restrict__ W, int k0) {
    int t = threadIdx.x;
#pragma unroll
    for (int i = 0; i < (KC * HH / 4) / TPB; i++) {
        int f = t + i * TPB;
        int k = f >> 5;
        int c = (f & 31) << 2;
        *(float4*)(Bs + k * HH + c) = *(const float4*)(W + (ll)(k0 + k) * HH + c);
    }
}

template<int KB, int LA>
__device__ __forceinline__ void mma8x4(const float* __restrict__ As,
                                       const float* __restrict__ Bs,
                                       int tr8, int tc4, float acc[8][4]) {
#pragma unroll
    for (int kb = 0; kb < KB; kb++) {
        float4 b0 = *(const float4*)(Bs + (kb * 4 + 0) * HH + tc4);
        float4 b1 = *(const float4*)(Bs + (kb * 4 + 1) * HH + tc4);
        float4 b2 = *(const float4*)(Bs + (kb * 4 + 2) * HH + tc4);
        float4 b3 = *(const float4*)(Bs + (kb * 4 + 3) * HH + tc4);
#pragma unroll
        for (int i = 0; i < 8; i++) {
            float4 a = *(const float4*)(As + (tr8 + i) * LA + kb * 4);
            acc[i][0] += a.x * b0.x; acc[i][1] += a.x * b0.y; acc[i][2] += a.x * b0.z; acc[i][3] += a.x * b0.w;
            acc[i][0] += a.y * b1.x; acc[i][1] += a.y * b1.y; acc[i][2] += a.y * b1.z; acc[i][3] += a.y * b1.w;
            acc[i][0] += a.z * b2.x; acc[i][1] += a.z * b2.y; acc[i][2] += a.z * b2.z; acc[i][3] += a.z * b2.w;
            acc[i][0] += a.w * b3.x; acc[i][1] += a.w * b3.y; acc[i][2] += a.w * b3.z; acc[i][3] += a.w * b3.w;
        }
    }
}

__device__ __forceinline__ float4 relu4(const float acc[4], float4 b) {
    float4 v;
    v.x = fmaxf(acc[0] + b.x, 0.f);
    v.y = fmaxf(acc[1] + b.y, 0.f);
    v.z = fmaxf(acc[2] + b.z, 0.f);
    v.w = fmaxf(acc[3] + b.w, 0.f);
    return v;
}

// ---------------- degree ----------------
__global__ void k_deg(const int* __restrict__ dst) {
    int e = blockIdx.x * blockDim.x + threadIdx.x;
    if (e < EE) atomicAdd(&g_deg[dst[e]], 1.f);
}

// ---------------- fused node encoder (+ agg zero for layer 0) ----------------
__global__ void __launch_bounds__(TPB) k_enc_fused(const float* __restrict__ x,
                                                   const float* __restrict__ W,
                                                   const float* __restrict__ b) {
    extern __shared__ uint32_t sm[];
    uint32_t* Ah  = sm + OFF_APH;
    uint32_t* Al  = sm + OFF_APL;
    uint32_t* B1h = sm + OFF_B1H;
    uint32_t* B1l = sm + OFF_B1L;
    uint32_t* B2h = sm + OFF_B2H;
    uint32_t* B2l = sm + OFF_B2L;
    float*    Cf  = (float*)(sm + OFF_CF);
    float*    As  = (float*)Ah;
    float*    Bs  = (float*)B1h;

    int t = threadIdx.x;
    int lane = t & 31, wid = t >> 5;
    int wm = (wid >> 1) << 4, wn = (wid & 1) << 6;
    int lr = lane >> 2, ka = lane & 3;
    int tr8 = (t >> 5) << 3, tc4 = (t & 31) << 2;
    int r = t >> 2, q = t & 3;
    int n0 = blockIdx.x * BM;
    int row = min(n0 + r, NN - 1);

    float4 z = make_float4(0.f, 0.f, 0.f, 0.f);
#pragma unroll
    for (int i = 0; i < 8; i++) {
        int f = t + i * TPB;
        int rr = n0 + (f >> 5);
        if (rr < NN)
            *(float4*)(g_agg + (ll)rr * HH + ((f & 31) << 2)) = z;
    }

    float acc[8][4] = {};
#pragma unroll 1
    for (int c = 0; c < 2; c++) {
        __syncthreads();
        const float* p = x + (ll)row * 64 + c * 32;
        *(float4*)(As + r * LDAS + q * 4)      = *(const float4*)(p + q * 4);
        *(float4*)(As + r * LDAS + 16 + q * 4) = *(const float4*)(p + 16 + q * 4);
        load_B<32>(Bs, W, c * 32);
        __syncthreads();
        mma8x4<8, LDAS>(As, Bs, tr8, tc4, acc);
    }
    __syncthreads();
    float4 bb = *(const float4*)(b + tc4);
#pragma unroll
    for (int i = 0; i < 8; i++) {
        float4 v = relu4(acc[i], bb);
        int rr = n0 + tr8 + i;
        *(float4*)(Cf + (tr8 + i) * LDA + tc4) = v;
        if (rr < NN)
            *(float4*)(g_h + (ll)rr * HH + tc4) = v;
    }
    p_passes(Ah, Al, B1h, B1l, B2h, B2l, Cf, 0, n0, wm, wn, lr, ka);
}

// ---------------- tf32 fused edge kernel: cp.async 3-stage B pipeline ----------------
// smem: As 128*LDA | Bstage[3] each (2 matrices x 32*LDB); CsM aliases As, CsE aliases Bstage
#define BSTG (2 * 32 * LDB)
#define EDGE_SMEM ((EBM * LDA + 3 * BSTG) * 4)
__global__ void __launch_bounds__(ETPB) k_edge_tf32(const int* __restrict__ src,
                                                    const int* __restrict__ dst,
                                                    int layer,
                                                    const float* __restrict__ bM,
                                                    const float* __restrict__ be,
                                                    const float* __restrict__ ea,
                                                    const float* __restrict__ be0,
                                                    int do_edge) {
    extern __shared__ uint32_t smem_u[];
    uint32_t* As = smem_u;
    uint32_t* BS = smem_u + EBM * LDA;
    float*    CsM = (float*)As;
    float*    CsE = (float*)BS;      // 3*BSTG = 26112 words >= 128*LDA = 16896

    const uint32_t* wm3_t = g_wm3_t + layer * 128 * HH;
    const uint32_t* we_t  = g_we_t  + layer * 128 * HH;

    int t = threadIdx.x;
    int lane = t & 31, wid = t >> 5;
    int wm = (wid >> 1) << 4;
    int wn = (wid & 1) << 6;
    int lr = lane >> 2, ka = lane & 3;
    ll e0 = (ll)blockIdx.x * EBM;

    // ---- issue B prefetch for chunks 0,1 immediately ----
#pragma unroll
    for (int pc = 0; pc < 2; pc++) {
        uint32_t* Bst = BS + pc * BSTG;
#pragma unroll
        for (int i = 0; i < 2; i++) {
            int ff = t + i * ETPB;
            int krow = ff >> 5, c4 = (ff & 31) << 2;
            cpa16(Bst + krow * LDB + c4, wm3_t + (ll)(pc * 32 + krow) * HH + c4);
            if (do_edge)
                cpa16(Bst + 32 * LDB + krow * LDB + c4,
                      we_t + (ll)(pc * 32 + krow) * HH + c4);
        }
        CP_COMMIT();
    }

    // ---- A stage ----
    if (layer == 0) {
        // in-tile edge encoder: As = tf32(relu(ea @ We0 + be0))
        // scratch in third B stage (not used until chunk 2 prefetch, issued later)
        uint32_t* EA = BS + 2 * BSTG;                 // 128*LDAP = 2560 words
        uint32_t* WB = BS + 2 * BSTG + 128 * LDAP;    // 16*LDB = 2176 words (total 4736 <= 8704)
        {
            int rr = t >> 2, qq = t & 3;
            float4 v = *(const float4*)(ea + (e0 + rr) * 16 + qq * 4);
            uint4 u;
            u.x = f2tf(v.x); u.y = f2tf(v.y); u.z = f2tf(v.z); u.w = f2tf(v.w);
            *(uint4*)(EA + rr * LDAP + qq * 4) = u;
        }
        {
            int krow = t >> 5, c4 = (t & 31) << 2;
            *(uint4*)(WB + krow * LDB + c4) = *(const uint4*)(g_we0_t + krow * HH + c4);
        }
        __syncthreads();
        float accW[8][4] = {};
#pragma unroll
        for (int ks = 0; ks < 2; ks++) {
            int kb = ks * 8 + ka;
            uint32_t a0 = EA[(wm + lr) * LDAP + kb];
            uint32_t a1 = EA[(wm + 8 + lr) * LDAP + kb];
            uint32_t a2 = EA[(wm + lr) * LDAP + kb + 4];
            uint32_t a3 = EA[(wm + 8 + lr) * LDAP + kb + 4];
#pragma unroll
            for (int nt = 0; nt < 8; nt++) {
                int nb = wn + nt * 8 + lr;
                uint32_t b0 = WB[(ks * 8 + ka) * LDB + nb];
                uint32_t b1 = WB[(ks * 8 + 4 + ka) * LDB + nb];
                mma_tf32(accW[nt], a0, a1, a2, a3, b0, b1);
            }
        }
#pragma unroll
        for (int nt = 0; nt < 8; nt++) {
            int col = wn + nt * 8 + (ka << 1);
            float2 bb = *(const float2*)(be0 + col);
            As[(wm + lr) * LDA + col]         = f2tf(fmaxf(accW[nt][0] + bb.x, 0.f));
            As[(wm + lr) * LDA + col + 1]     = f2tf(fmaxf(accW[nt][1] + bb.y, 0.f));
            As[(wm + 8 + lr) * LDA + col]     = f2tf(fmaxf(accW[nt][2] + bb.x, 0.f));
            As[(wm + 8 + lr) * LDA + col + 1] = f2tf(fmaxf(accW[nt][3] + bb.y, 0.f));
        }
    } else {
#pragma unroll
        for (int i = 0; i < 8; i++) {
            int f = t + i * ETPB;
            int row = f >> 5, c4 = (f & 31) << 2;
            *(uint4*)(As + row * LDA + c4) = *(const uint4*)(g_e + (e0 + row) * HH + c4);
        }
    }

    float accM[8][4], accE[8][4];
#pragma unroll
    for (int i = 0; i < 8; i++)
#pragma unroll
        for (int j = 0; j < 4; j++) { accM[i][j] = 0.f; accE[i][j] = 0.f; }

    // ---- pipelined mainloop (fully unrolled; wait_group imm) ----
#pragma unroll
    for (int kc = 0; kc < 4; kc++) {
        if (kc < 3) { CP_WAIT(1); } else { CP_WAIT(0); }
        __syncthreads();   // all threads' copies for chunk kc visible; prior reads done
        if (kc + 2 < 4) {
            uint32_t* Bst = BS + ((kc + 2) % 3) * BSTG;
#pragma unroll
            for (int i = 0; i < 2; i++) {
                int ff = t + i * ETPB;
                int krow = ff >> 5, c4 = (ff & 31) << 2;
                cpa16(Bst + krow * LDB + c4, wm3_t + (ll)((kc + 2) * 32 + krow) * HH + c4);
                if (do_edge)
                    cpa16(Bst + 32 * LDB + krow * LDB + c4,
                          we_t + (ll)((kc + 2) * 32 + krow) * HH + c4);
            }
            CP_COMMIT();
        }
        const uint32_t* B1 = BS + (kc % 3) * BSTG;
        const uint32_t* B2 = B1 + 32 * LDB;
#pragma unroll
        for (int ks = 0; ks < 4; ks++) {
            int kb = kc * 32 + ks * 8 + ka;
            uint32_t a0 = As[(wm + lr) * LDA + kb];
            uint32_t a1 = As[(wm + 8 + lr) * LDA + kb];
            uint32_t a2 = As[(wm + lr) * LDA + kb + 4];
            uint32_t a3 = As[(wm + 8 + lr) * LDA + kb + 4];
#pragma unroll
            for (int nt = 0; nt < 8; nt++) {
                int nb = wn + nt * 8 + lr;
                uint32_t b0 = B1[(ks * 8 + ka) * LDB + nb];
                uint32_t b1 = B1[(ks * 8 + 4 + ka) * LDB + nb];
                mma_tf32(accM[nt], a0, a1, a2, a3, b0, b1);
            }
            if (do_edge) {
#pragma unroll
                for (int nt = 0; nt < 8; nt++) {
                    int nb = wn + nt * 8 + lr;
                    uint32_t b0 = B2[(ks * 8 + ka) * LDB + nb];
                    uint32_t b1 = B2[(ks * 8 + 4 + ka) * LDB + nb];
                    mma_tf32(accE[nt], a0, a1, a2, a3, b0, b1);
                }
            }
        }
    }

    // ---- merged epilogue: frags -> CsM (aliases As) and CsE (aliases BS) ----
    __syncthreads();
#pragma unroll
    for (int nt = 0; nt < 8; nt++) {
        int col = wn + nt * 8 + (ka << 1);
        *(float2*)(CsM + (wm + lr) * LDA + col)     = make_float2(accM[nt][0], accM[nt][1]);
        *(float2*)(CsM + (wm + 8 + lr) * LDA + col) = make_float2(accM[nt][2], accM[nt][3]);
        if (do_edge) {
            *(float2*)(CsE + (wm + lr) * LDA + col)     = make_float2(accE[nt][0], accE[nt][1]);
            *(float2*)(CsE + (wm + 8 + lr) * LDA + col) = make_float2(accE[nt][2], accE[nt][3]);
        }
    }
    __syncthreads();
#pragma unroll
    for (int i = 0; i < 8; i++) {
        int f = t + i * ETPB;
        int row = f >> 5, c4 = (f & 31) << 2;
        int ge = (int)e0 + row;
        int d = dst[ge], s = src[ge];
        float4 cM = *(const float4*)(CsM + row * LDA + c4);
        float4 bb = *(const float4*)(bM + c4);
        float4 p1 = *(const float4*)(g_p1 + (ll)d * HH + c4);
        float4 p2 = *(const float4*)(g_p2 + (ll)s * HH + c4);
        if (do_edge) {
            // independent e-store overlaps the p1/p2 gather latency
            float4 cE  = *(const float4*)(CsE + row * LDA + c4);
            float4 bb2 = *(const float4*)(be + c4);
            uint4 u;
            u.x = f2tf(fmaxf(cE.x + bb2.x, 0.f));
            u.y = f2tf(fmaxf(cE.y + bb2.y, 0.f));
            u.z = f2tf(fmaxf(cE.z + bb2.z, 0.f));
            u.w = f2tf(fmaxf(cE.w + bb2.w, 0.f));
            *(uint4*)(g_e + (e0 + row) * HH + c4) = u;
        }
        float4 v;
        v.x = fmaxf(cM.x + bb.x + p1.x + p2.x, 0.f);
        v.y = fmaxf(cM.y + bb.y + p1.y + p2.y, 0.f);
        v.z = fmaxf(cM.z + bb.z + p1.z + p2.z, 0.f);
        v.w = fmaxf(cM.w + bb.w + p1.w + p2.w, 0.f);
        atomicAdd((float4*)(g_agg + (ll)d * HH + c4), v);
    }
}

// ---------------- fused update (3xBF16, BM=64) + agg zeroing ----------------
__global__ void __launch_bounds__(TPB) k_update_fused(int layer,
                                                      const float* __restrict__ bU,
                                                      const float* __restrict__ bn,
                                                      int has_next) {
    extern __shared__ uint32_t sm[];
    uint32_t* Ah  = sm + OFF_APH;
    uint32_t* Al  = sm + OFF_APL;
    uint32_t* B1h = sm + OFF_B1H;
    uint32_t* B1l = sm + OFF_B1L;
    uint32_t* B2h = sm + OFF_B2H;
    uint32_t* B2l = sm + OFF_B2L;
    float*    Cf  = (float*)(sm + OFF_CF);

    const uint32_t* wu_h = g_wu_h + layer * 128 * HH;
    const uint32_t* wu_l = g_wu_l + layer * 128 * HH;
    const uint32_t* wn_h = g_wn_h + layer * 64 * HH;
    const uint32_t* wn_l = g_wn_l + layer * 64 * HH;

    int t = threadIdx.x;
    int lane = t & 31, wid = t >> 5;
    int wm = (wid >> 1) << 4, wn = (wid & 1) << 6;
    int lr = lane >> 2, ka = lane & 3;
    int r = t >> 2, q = t & 3;
    int n0 = blockIdx.x * BM;
    int row = min(n0 + r, NN - 1);
    float rd = 1.f / fmaxf(g_deg[row], 1.f);

    float acc[8][4];
#pragma unroll
    for (int i = 0; i < 8; i++)
#pragma unroll
        for (int j = 0; j < 4; j++) acc[i][j] = 0.f;
#pragma unroll 1
    for (int c = 0; c < 8; c++) {
        __syncthreads();
        const float* p = (c < 4) ? (g_h + (ll)row * HH + c * 32)
                                 : (g_agg + (ll)row * HH + (c - 4) * 32);
        float sc = (c < 4) ? 1.f : rd;
        float4 v0 = *(const float4*)(p + q * 4);
        float4 v1 = *(const float4*)(p + 16 + q * 4);
        v0.x *= sc; v0.y *= sc; v0.z *= sc; v0.w *= sc;
        v1.x *= sc; v1.y *= sc; v1.z *= sc; v1.w *= sc;
        stage_Abf(Ah, Al, r, q, v0, v1);
        stage_Bpre(B1h, B1l, wu_h, wu_l, c * 16);
        __syncthreads();
        mma3_bf(Ah, Al, B1h, B1l, wm, wn, lr, ka, acc);
    }
    frag_relu_toCf(Cf, acc, bU, wm, wn, lr, ka);

    {
        float4 z = make_float4(0.f, 0.f, 0.f, 0.f);
#pragma unroll
        for (int i = 0; i < 8; i++) {
            int f = t + i * TPB;
            int rr = n0 + (f >> 5);
            if (rr < NN)
                *(float4*)(g_agg + (ll)rr * HH + ((f & 31) << 2)) = z;
        }
    }

#pragma unroll
    for (int i = 0; i < 8; i++)
#pragma unroll
        for (int j = 0; j < 4; j++) acc[i][j] = 0.f;
#pragma unroll 1
    for (int kc = 0; kc < 4; kc++) {
        __syncthreads();
        stage_Abf_fromCf(Ah, Al, Cf, kc);
        stage_Bpre(B1h, B1l, wn_h, wn_l, kc * 16);
        __syncthreads();
        mma3_bf(Ah, Al, B1h, B1l, wm, wn, lr, ka, acc);
    }
    __syncthreads();
    frag_relu_toCf(Cf, acc, bn, wm, wn, lr, ka);
    __syncthreads();
#pragma unroll
    for (int i = 0; i < 8; i++) {
        int f = t + i * TPB;
        int rr = f >> 5, c4 = (f & 31) << 2;
        int gr = n0 + rr;
        if (gr < NN)
            *(float4*)(g_h + (ll)gr * HH + c4) = *(const float4*)(Cf + rr * LDA + c4);
    }

    if (has_next)
        p_passes(Ah, Al, B1h, B1l, B2h, B2l, Cf, layer + 1, n0, wm, wn, lr, ka);
}

// ---------------- global mean pool ----------------
__global__ void k_pool(const int* __restrict__ bvec) {
    int t = blockIdx.x * blockDim.x + threadIdx.x;
    int c4 = (t & 31) << 2;
    int nb = (t >> 5) * 16;
    if (nb >= NN) return;
    int end = min(nb + 16, NN);
    int g = bvec[nb];
    float4 s = make_float4(0.f, 0.f, 0.f, 0.f);
    float cnt = 0.f;
    for (int n = nb; n < end; n++) {
        int gn = bvec[n];
        if (gn != g) {
            atomicAdd((float4*)(g_pool + g * HH + c4), s);
            if (c4 == 0) atomicAdd(&g_cnt[g], cnt);
            s = make_float4(0.f, 0.f, 0.f, 0.f);
            cnt = 0.f;
            g = gn;
        }
        float4 hv = *(const float4*)(g_h + (ll)n * HH + c4);
        s.x += hv.x; s.y += hv.y; s.z += hv.z; s.w += hv.w;
        cnt += 1.f;
    }
    atomicAdd((float4*)(g_pool + g * HH + c4), s);
    if (c4 == 0) atomicAdd(&g_cnt[g], cnt);
}

__global__ void k_head(const float* __restrict__ Wh, const float* __restrict__ bh,
                       float* __restrict__ out) {
    int g = threadIdx.x;
    float rc = 1.f / fmaxf(g_cnt[g], 1.f);
    float acc = bh[0];
#pragma unroll
    for (int k = 0; k < HH; k++)
        acc += g_pool[g * HH + k] * rc * Wh[k];
    out[g] = acc;
}

// ---------------- launch ----------------
extern "C" void kernel_launch(void* const* d_in, const int* in_sizes, int n_in,
                              void* d_out, int out_size) {
    const float* x    = (const float*)d_in[0];
    const int*   ei   = (const int*)d_in[1];
    const float* ea   = (const float*)d_in[2];
    const int*   bvec = (const int*)d_in[3];
    const float* Wn0  = (const float*)d_in[4];
    const float* bn0  = (const float*)d_in[5];
    const float* We0  = (const float*)d_in[6];
    const float* be0  = (const float*)d_in[7];
    const float* WM   = (const float*)d_in[8];
    const float* bM   = (const float*)d_in[9];
    const float* WU   = (const float*)d_in[10];
    const float* bU   = (const float*)d_in[11];
    const float* Wn   = (const float*)d_in[12];
    const float* bn   = (const float*)d_in[13];
    const float* We   = (const float*)d_in[14];
    const float* be   = (const float*)d_in[15];
    const float* Wh   = (const float*)d_in[16];
    const float* bh   = (const float*)d_in[17];
    float* out = (float*)d_out;

    const int* src = ei;
    const int* dst = ei + EE;

    static int attr_done = 0;
    if (!attr_done) {
        cudaFuncSetAttribute(k_edge_tf32, cudaFuncAttributeMaxDynamicSharedMemorySize,
                             EDGE_SMEM);
        cudaFuncSetAttribute(k_enc_fused, cudaFuncAttributeMaxDynamicSharedMemorySize,
                             NODE_SMEM);
        cudaFuncSetAttribute(k_update_fused, cudaFuncAttributeMaxDynamicSharedMemorySize,
                             NODE_SMEM);
        attr_done = 1;
    }

    int prep_threads = 3 * 40960 + 2 * 3 * 16384 + 16 * HH + NN;
    k_prep<<<(prep_threads + 255) / 256, 256>>>(WM, WU, Wn, We, We0);

    k_deg<<<(EE + 255) / 256, 256>>>(dst);

    int nblk = (NN + BM - 1) / BM;
    k_enc_fused<<<nblk, TPB, NODE_SMEM>>>(x, Wn0, bn0);

    for (int l = 0; l < 3; l++) {
        k_edge_tf32<<<EE / EBM, ETPB, EDGE_SMEM>>>(src, dst, l, bM + l * HH,
                                                   be + l * HH, ea, be0,
                                                   l < 2 ? 1 : 0);
        k_update_fused<<<nblk, TPB, NODE_SMEM>>>(l, bU + l * HH, bn + l * HH,
                                                 l < 2 ? 1 : 0);
    }

    int pool_threads = ((NN + 15) / 16) * 32;
    k_pool<<<(pool_threads + 255) / 256, 256>>>(bvec);
    k_head<<<1, GG>>>(Wh, bh, out);
}

// round 16
// speedup vs baseline: 1.3509x; 1.3509x over previous
#include <cuda_runtime.h>
#include <cstdint>

#define NN 100000
#define EE 640000
#define GG 256
#define HH 128
#define TPB 256
#define BM 64
#define EBM 128
#define ETPB 512
#define LDA 132
#define LDB 136
#define LDAS 36
#define LDAP 20
#define LDBP 136

typedef long long ll;

// ---------------- scratch ----------------
__device__ float g_h[NN * HH];
__device__ float g_agg[NN * HH];
__device__ float g_p1[NN * HH];
__device__ float g_p2[NN * HH];
__device__ uint32_t g_e[(ll)EE * HH];     // e stored as tf32 bit patterns
__device__ float g_deg[NN];
__device__ float g_pool[GG * HH];
__device__ float g_cnt[GG];

// pre-converted weights
__device__ uint32_t g_wu_h[3 * 128 * HH],   g_wu_l[3 * 128 * HH];
__device__ uint32_t g_wn_h[3 * 64 * HH],    g_wn_l[3 * 64 * HH];
__device__ uint32_t g_wm12_h[3 * 128 * HH], g_wm12_l[3 * 128 * HH];
__device__ uint32_t g_wm3_t[3 * 128 * HH];
__device__ uint32_t g_we_t[3 * 128 * HH];
__device__ uint32_t g_we0_t[16 * HH];

// ---------------- helpers ----------------
__device__ __forceinline__ uint32_t f2tf(float f) {
    uint32_t u;
    asm("cvt.rna.tf32.f32 %0, %1;" : "=r"(u) : "f"(f));
    return u;
}
__device__ __forceinline__ void mma_tf32(float* c, uint32_t a0, uint32_t a1,
                                         uint32_t a2, uint32_t a3,
                                         uint32_t b0, uint32_t b1) {
    asm volatile(
        "mma.sync.aligned.m16n8k8.row.col.f32.tf32.tf32.f32 "
        "{%0,%1,%2,%3}, {%4,%5,%6,%7}, {%8,%9}, {%0,%1,%2,%3};\n"
        : "+f"(c[0]), "+f"(c[1]), "+f"(c[2]), "+f"(c[3])
        : "r"(a0), "r"(a1), "r"(a2), "r"(a3), "r"(b0), "r"(b1));
}
__device__ __forceinline__ void split_pack(float v0, float v1,
                                           uint32_t& ph, uint32_t& pl) {
    uint32_t h;
    asm("cvt.rn.bf16x2.f32 %0, %1, %2;" : "=r"(h) : "f"(v1), "f"(v0));
    float h0 = __uint_as_float(h << 16);
    float h1 = __uint_as_float(h & 0xffff0000u);
    asm("cvt.rn.bf16x2.f32 %0, %1, %2;" : "=r"(pl) : "f"(v1 - h1), "f"(v0 - h0));
    ph = h;
}
__device__ __forceinline__ void mma_bf16(float* c, uint32_t a0, uint32_t a1,
                                         uint32_t a2, uint32_t a3,
                                         uint32_t b0, uint32_t b1) {
    asm volatile(
        "mma.sync.aligned.m16n8k16.row.col.f32.bf16.bf16.f32 "
        "{%0,%1,%2,%3}, {%4,%5,%6,%7}, {%8,%9}, {%0,%1,%2,%3};\n"
        : "+f"(c[0]), "+f"(c[1]), "+f"(c[2]), "+f"(c[3])
        : "r"(a0), "r"(a1), "r"(a2), "r"(a3), "r"(b0), "r"(b1));
}

// ---------------- weight prep + misc zero (one launch) ----------------
__global__ void k_prep(const float* __restrict__ WM, const float* __restrict__ WU,
                       const float* __restrict__ Wn, const float* __restrict__ We,
                       const float* __restrict__ We0) {
    int i = blockIdx.x * blockDim.x + threadIdx.x;
    if (i < 3 * 40960) {
        int l = i / 40960, j = i % 40960;
        const float* W;
        uint32_t *dh, *dl;
        if (j < 16384)      { W = WU + (ll)l * 256 * HH; dh = g_wu_h + l * 16384;  dl = g_wu_l + l * 16384; }
        else if (j < 24576) { j -= 16384; W = Wn + (ll)l * 128 * HH; dh = g_wn_h + l * 8192; dl = g_wn_l + l * 8192; }
        else                { j -= 24576; W = WM + (ll)l * 384 * HH; dh = g_wm12_h + l * 16384; dl = g_wm12_l + l * 16384; }
        int kp = j >> 7, n = j & 127;
        uint32_t h, lo;
        split_pack(W[(ll)(2 * kp) * HH + n], W[(ll)(2 * kp + 1) * HH + n], h, lo);
        dh[j] = h; dl[j] = lo;
    } else {
        int k = i - 3 * 40960;
        if (k < 3 * 16384) {
            int l = k / 16384, j = k % 16384;
            g_wm3_t[k] = f2tf(WM[(ll)l * 384 * HH + 256 * HH + j]);
        } else {
            k -= 3 * 16384;
            if (k < 3 * 16384) {
                g_we_t[k] = f2tf(We[k]);
            } else {
                k -= 3 * 16384;
                if (k < 16 * HH) {
                    g_we0_t[k] = f2tf(We0[k]);
                } else {
                    k -= 16 * HH;
                    if (k < NN) g_deg[k] = 0.f;
                    if (k < GG * HH) g_pool[k] = 0.f;
                    if (k < GG) g_cnt[k] = 0.f;
                }
            }
        }
    }
}

// ---------------- node-kernel smem partition (BM=64) ----------------
#define OFF_APH 0
#define OFF_APL (BM * LDAP)
#define OFF_B1H (2 * BM * LDAP)
#define OFF_B1L (OFF_B1H + 16 * LDBP)
#define OFF_B2H (OFF_B1H + 2 * 16 * LDBP)
#define OFF_B2L (OFF_B1H + 3 * 16 * LDBP)
#define OFF_CF  (OFF_B1H + 4 * 16 * LDBP)
#define NODE_SMEM ((OFF_CF + BM * LDA) * 4)

__device__ __forceinline__ void stage_Bpre(uint32_t* Bh, uint32_t* Bl,
                                           const uint32_t* __restrict__ GH,
                                           const uint32_t* __restrict__ GL, int kp0) {
    int t = threadIdx.x;
#pragma unroll
    for (int i = 0; i < 2; i++) {
        int f = t + i * TPB;
        int kp = f >> 5, n = (f & 31) << 2;
        *(uint4*)(Bh + kp * LDBP + n) = *(const uint4*)(GH + (ll)(kp0 + kp) * HH + n);
        *(uint4*)(Bl + kp * LDBP + n) = *(const uint4*)(GL + (ll)(kp0 + kp) * HH + n);
    }
}

__device__ __forceinline__ void stage_Abf(uint32_t* Ah, uint32_t* Al,
                                          int r, int q, float4 v0, float4 v1) {
    uint32_t h0, l0, h1, l1;
    split_pack(v0.x, v0.y, h0, l0);
    split_pack(v0.z, v0.w, h1, l1);
    *(uint2*)(Ah + r * LDAP + 2 * q) = make_uint2(h0, h1);
    *(uint2*)(Al + r * LDAP + 2 * q) = make_uint2(l0, l1);
    split_pack(v1.x, v1.y, h0, l0);
    split_pack(v1.z, v1.w, h1, l1);
    *(uint2*)(Ah + r * LDAP + 8 + 2 * q) = make_uint2(h0, h1);
    *(uint2*)(Al + r * LDAP + 8 + 2 * q) = make_uint2(l0, l1);
}

__device__ __forceinline__ void stage_Abf_fromCf(uint32_t* Ah, uint32_t* Al,
                                                 const float* Cf, int kc) {
    int t = threadIdx.x;
    int r = t >> 2, q = t & 3;
    float4 v0 = *(const float4*)(Cf + r * LDA + kc * 32 + q * 4);
    float4 v1 = *(const float4*)(Cf + r * LDA + kc * 32 + 16 + q * 4);
    stage_Abf(Ah, Al, r, q, v0, v1);
}

__device__ __forceinline__ void mma3_bf(const uint32_t* Ah, const uint32_t* Al,
                                        const uint32_t* Bh, const uint32_t* Bl,
                                        int wm, int wn, int lr, int ka,
                                        float acc[8][4]) {
#pragma unroll
    for (int ks = 0; ks < 2; ks++) {
        int kpb = ks * 8;
        uint32_t ah0 = Ah[(wm + lr) * LDAP + kpb + ka];
        uint32_t ah1 = Ah[(wm + 8 + lr) * LDAP + kpb + ka];
        uint32_t ah2 = Ah[(wm + lr) * LDAP + kpb + ka + 4];
        uint32_t ah3 = Ah[(wm + 8 + lr) * LDAP + kpb + ka + 4];
        uint32_t al0 = Al[(wm + lr) * LDAP + kpb + ka];
        uint32_t al1 = Al[(wm + 8 + lr) * LDAP + kpb + ka];
        uint32_t al2 = Al[(wm + lr) * LDAP + kpb + ka + 4];
        uint32_t al3 = Al[(wm + 8 + lr) * LDAP + kpb + ka + 4];
#pragma unroll
        for (int nt = 0; nt < 8; nt++) {
            int nb = wn + nt * 8 + lr;
            uint32_t bh0 = Bh[(kpb + ka) * LDBP + nb];
            uint32_t bh1 = Bh[(kpb + ka + 4) * LDBP + nb];
            uint32_t bl0 = Bl[(kpb + ka) * LDBP + nb];
            uint32_t bl1 = Bl[(kpb + ka + 4) * LDBP + nb];
            mma_bf16(acc[nt], ah0, ah1, ah2, ah3, bh0, bh1);
            mma_bf16(acc[nt], al0, al1, al2, al3, bh0, bh1);
            mma_bf16(acc[nt], ah0, ah1, ah2, ah3, bl0, bl1);
        }
    }
}

__device__ __forceinline__ void mma3_bf_dual(const uint32_t* Ah, const uint32_t* Al,
                                             const uint32_t* B1h, const uint32_t* B1l,
                                             const uint32_t* B2h, const uint32_t* B2l,
                                             int wm, int wn, int lr, int ka,
                                             float accA[8][4], float accB[8][4]) {
#pragma unroll
    for (int ks = 0; ks < 2; ks++) {
        int kpb = ks * 8;
        uint32_t ah0 = Ah[(wm + lr) * LDAP + kpb + ka];
        uint32_t ah1 = Ah[(wm + 8 + lr) * LDAP + kpb + ka];
        uint32_t ah2 = Ah[(wm + lr) * LDAP + kpb + ka + 4];
        uint32_t ah3 = Ah[(wm + 8 + lr) * LDAP + kpb + ka + 4];
        uint32_t al0 = Al[(wm + lr) * LDAP + kpb + ka];
        uint32_t al1 = Al[(wm + 8 + lr) * LDAP + kpb + ka];
        uint32_t al2 = Al[(wm + lr) * LDAP + kpb + ka + 4];
        uint32_t al3 = Al[(wm + 8 + lr) * LDAP + kpb + ka + 4];
#pragma unroll
        for (int nt = 0; nt < 8; nt++) {
            int nb = wn + nt * 8 + lr;
            uint32_t bh0 = B1h[(kpb + ka) * LDBP + nb];
            uint32_t bh1 = B1h[(kpb + ka + 4) * LDBP + nb];
            uint32_t bl0 = B1l[(kpb + ka) * LDBP + nb];
            uint32_t bl1 = B1l[(kpb + ka + 4) * LDBP + nb];
            mma_bf16(accA[nt], ah0, ah1, ah2, ah3, bh0, bh1);
            mma_bf16(accA[nt], al0, al1, al2, al3, bh0, bh1);
            mma_bf16(accA[nt], ah0, ah1, ah2, ah3, bl0, bl1);
            bh0 = B2h[(kpb + ka) * LDBP + nb];
            bh1 = B2h[(kpb + ka + 4) * LDBP + nb];
            bl0 = B2l[(kpb + ka) * LDBP + nb];
            bl1 = B2l[(kpb + ka + 4) * LDBP + nb];
            mma_bf16(accB[nt], ah0, ah1, ah2, ah3, bh0, bh1);
            mma_bf16(accB[nt], al0, al1, al2, al3, bh0, bh1);
            mma_bf16(accB[nt], ah0, ah1, ah2, ah3, bl0, bl1);
        }
    }
}

__device__ __forceinline__ void frag_relu_toCf(float* Cf, const float acc[8][4],
                                               const float* __restrict__ bias,
                                               int wm, int wn, int lr, int ka) {
#pragma unroll
    for (int nt = 0; nt < 8; nt++) {
        int col = wn + nt * 8 + (ka << 1);
        float2 bb = *(const float2*)(bias + col);
        Cf[(wm + lr) * LDA + col]         = fmaxf(acc[nt][0] + bb.x, 0.f);
        Cf[(wm + lr) * LDA + col + 1]     = fmaxf(acc[nt][1] + bb.y, 0.f);
        Cf[(wm + 8 + lr) * LDA + col]     = fmaxf(acc[nt][2] + bb.x, 0.f);
        Cf[(wm + 8 + lr) * LDA + col + 1] = fmaxf(acc[nt][3] + bb.y, 0.f);
    }
}

__device__ __forceinline__ void p_passes(uint32_t* Ah, uint32_t* Al,
                                         uint32_t* B1h, uint32_t* B1l,
                                         uint32_t* B2h, uint32_t* B2l, float* Cf,
                                         int layer,
                                         int n0, int wm, int wn, int lr, int ka) {
    const uint32_t* GH1 = g_wm12_h + layer * 128 * HH;
    const uint32_t* GL1 = g_wm12_l + layer * 128 * HH;
    const uint32_t* GH2 = GH1 + 64 * HH;
    const uint32_t* GL2 = GL1 + 64 * HH;
    float accA[8][4], accB[8][4];
#pragma unroll
    for (int i = 0; i < 8; i++)
#pragma unroll
        for (int j = 0; j < 4; j++) { accA[i][j] = 0.f; accB[i][j] = 0.f; }
#pragma unroll 1
    for (int kc = 0; kc < 4; kc++) {
        __syncthreads();
        stage_Abf_fromCf(Ah, Al, Cf, kc);
        stage_Bpre(B1h, B1l, GH1, GL1, kc * 16);
        stage_Bpre(B2h, B2l, GH2, GL2, kc * 16);
        __syncthreads();
        mma3_bf_dual(Ah, Al, B1h, B1l, B2h, B2l, wm, wn, lr, ka, accA, accB);
    }
    int row0 = n0 + wm + lr, row1 = row0 + 8;
#pragma unroll
    for (int nt = 0; nt < 8; nt++) {
        int col = wn + nt * 8 + (ka << 1);
        if (row0 < NN) {
            *(float2*)(g_p1 + (ll)row0 * HH + col) = make_float2(accA[nt][0], accA[nt][1]);
            *(float2*)(g_p2 + (ll)row0 * HH + col) = make_float2(accB[nt][0], accB[nt][1]);
        }
        if (row1 < NN) {
            *(float2*)(g_p1 + (ll)row1 * HH + col) = make_float2(accA[nt][2], accA[nt][3]);
            *(float2*)(g_p2 + (ll)row1 * HH + col) = make_float2(accB[nt][2], accB[nt][3]);
        }
    }
}

// ---------------- fp32 helpers (node encoder) ----------------
template<int KC>
__device__ __forceinline__ void load_B(float* Bs, const float* __restrict__ W, int k0) {
    int t = threadIdx.x;
#pragma unroll
    for (int i = 0; i < (KC * HH / 4) / TPB; i++) {
        int f = t + i * TPB;
        int k = f >> 5;
        int c = (f & 31) << 2;
        *(float4*)(Bs + k * HH + c) = *(const float4*)(W + (ll)(k0 + k) * HH + c);
    }
}

template<int KB, int LA>
__device__ __forceinline__ void mma8x4(const float* __restrict__ As,
                                       const float* __restrict__ Bs,
                                       int tr8, int tc4, float acc[8][4]) {
#pragma unroll
    for (int kb = 0; kb < KB; kb++) {
        float4 b0 = *(const float4*)(Bs + (kb * 4 + 0) * HH + tc4);
        float4 b1 = *(const float4*)(Bs + (kb * 4 + 1) * HH + tc4);
        float4 b2 = *(const float4*)(Bs + (kb * 4 + 2) * HH + tc4);
        float4 b3 = *(const float4*)(Bs + (kb * 4 + 3) * HH + tc4);
#pragma unroll
        for (int i = 0; i < 8; i++) {
            float4 a = *(const float4*)(As + (tr8 + i) * LA + kb * 4);
            acc[i][0] += a.x * b0.x; acc[i][1] += a.x * b0.y; acc[i][2] += a.x * b0.z; acc[i][3] += a.x * b0.w;
            acc[i][0] += a.y * b1.x; acc[i][1] += a.y * b1.y; acc[i][2] += a.y * b1.z; acc[i][3] += a.y * b1.w;
            acc[i][0] += a.z * b2.x; acc[i][1] += a.z * b2.y; acc[i][2] += a.z * b2.z; acc[i][3] += a.z * b2.w;
            acc[i][0] += a.w * b3.x; acc[i][1] += a.w * b3.y; acc[i][2] += a.w * b3.z; acc[i][3] += a.w * b3.w;
        }
    }
}

__device__ __forceinline__ float4 relu4(const float acc[4], float4 b) {
    float4 v;
    v.x = fmaxf(acc[0] + b.x, 0.f);
    v.y = fmaxf(acc[1] + b.y, 0.f);
    v.z = fmaxf(acc[2] + b.z, 0.f);
    v.w = fmaxf(acc[3] + b.w, 0.f);
    return v;
}

// ---------------- degree ----------------
__global__ void k_deg(const int* __restrict__ dst) {
    int e = blockIdx.x * blockDim.x + threadIdx.x;
    if (e < EE) atomicAdd(&g_deg[dst[e]], 1.f);
}

// ---------------- fused node encoder (+ agg zero for layer 0) ----------------
__global__ void __launch_bounds__(TPB) k_enc_fused(const float* __restrict__ x,
                                                   const float* __restrict__ W,
                                                   const float* __restrict__ b) {
    extern __shared__ uint32_t sm[];
    uint32_t* Ah  = sm + OFF_APH;
    uint32_t* Al  = sm + OFF_APL;
    uint32_t* B1h = sm + OFF_B1H;
    uint32_t* B1l = sm + OFF_B1L;
    uint32_t* B2h = sm + OFF_B2H;
    uint32_t* B2l = sm + OFF_B2L;
    float*    Cf  = (float*)(sm + OFF_CF);
    float*    As  = (float*)Ah;
    float*    Bs  = (float*)B1h;

    int t = threadIdx.x;
    int lane = t & 31, wid = t >> 5;
    int wm = (wid >> 1) << 4, wn = (wid & 1) << 6;
    int lr = lane >> 2, ka = lane & 3;
    int tr8 = (t >> 5) << 3, tc4 = (t & 31) << 2;
    int r = t >> 2, q = t & 3;
    int n0 = blockIdx.x * BM;
    int row = min(n0 + r, NN - 1);

    float4 z = make_float4(0.f, 0.f, 0.f, 0.f);
#pragma unroll
    for (int i = 0; i < 8; i++) {
        int f = t + i * TPB;
        int rr = n0 + (f >> 5);
        if (rr < NN)
            *(float4*)(g_agg + (ll)rr * HH + ((f & 31) << 2)) = z;
    }

    float acc[8][4] = {};
#pragma unroll 1
    for (int c = 0; c < 2; c++) {
        __syncthreads();
        const float* p = x + (ll)row * 64 + c * 32;
        *(float4*)(As + r * LDAS + q * 4)      = *(const float4*)(p + q * 4);
        *(float4*)(As + r * LDAS + 16 + q * 4) = *(const float4*)(p + 16 + q * 4);
        load_B<32>(Bs, W, c * 32);
        __syncthreads();
        mma8x4<8, LDAS>(As, Bs, tr8, tc4, acc);
    }
    __syncthreads();
    float4 bb = *(const float4*)(b + tc4);
#pragma unroll
    for (int i = 0; i < 8; i++) {
        float4 v = relu4(acc[i], bb);
        int rr = n0 + tr8 + i;
        *(float4*)(Cf + (tr8 + i) * LDA + tc4) = v;
        if (rr < NN)
            *(float4*)(g_h + (ll)rr * HH + tc4) = v;
    }
    p_passes(Ah, Al, B1h, B1l, B2h, B2l, Cf, 0, n0, wm, wn, lr, ka);
}

// ---------------- tf32 fused edge kernel: R14 mainloop + merged epilogue ----------------
// smem: As 128*LDA | B1,B2 (2*32*LDB) | extra 8192 words so CsE (starting at B1) = 128*LDA
#define EDGE_SMEM ((EBM * LDA + 2 * 32 * LDB + 8192) * 4)
__global__ void __launch_bounds__(ETPB) k_edge_tf32(const int* __restrict__ src,
                                                    const int* __restrict__ dst,
                                                    int layer,
                                                    const float* __restrict__ bM,
                                                    const float* __restrict__ be,
                                                    const float* __restrict__ ea,
                                                    const float* __restrict__ be0,
                                                    int do_edge) {
    extern __shared__ uint32_t smem_u[];
    uint32_t* As = smem_u;
    uint32_t* B1 = smem_u + EBM * LDA;
    uint32_t* B2 = B1 + 32 * LDB;
    float*    CsM = (float*)As;
    float*    CsE = (float*)B1;     // B1+B2+extra = 16896 words = 128*LDA

    const uint32_t* wm3_t = g_wm3_t + layer * 128 * HH;
    const uint32_t* we_t  = g_we_t  + layer * 128 * HH;

    int t = threadIdx.x;
    int lane = t & 31, wid = t >> 5;
    int wm = (wid >> 1) << 4;
    int wn = (wid & 1) << 6;
    int lr = lane >> 2, ka = lane & 3;
    ll e0 = (ll)blockIdx.x * EBM;

    if (layer == 0) {
        // in-tile edge encoder: As = tf32(relu(ea @ We0 + be0))
        uint32_t* EA = B1;
        uint32_t* WB = B2;
        {
            int rr = t >> 2, qq = t & 3;
            float4 v = *(const float4*)(ea + (e0 + rr) * 16 + qq * 4);
            uint4 u;
            u.x = f2tf(v.x); u.y = f2tf(v.y); u.z = f2tf(v.z); u.w = f2tf(v.w);
            *(uint4*)(EA + rr * LDAP + qq * 4) = u;
        }
        {
            int krow = t >> 5, c4 = (t & 31) << 2;
            *(uint4*)(WB + krow * LDB + c4) = *(const uint4*)(g_we0_t + krow * HH + c4);
        }
        __syncthreads();
        float accW[8][4] = {};
#pragma unroll
        for (int ks = 0; ks < 2; ks++) {
            int kb = ks * 8 + ka;
            uint32_t a0 = EA[(wm + lr) * LDAP + kb];
            uint32_t a1 = EA[(wm + 8 + lr) * LDAP + kb];
            uint32_t a2 = EA[(wm + lr) * LDAP + kb + 4];
            uint32_t a3 = EA[(wm + 8 + lr) * LDAP + kb + 4];
#pragma unroll
            for (int nt = 0; nt < 8; nt++) {
                int nb = wn + nt * 8 + lr;
                uint32_t b0 = WB[(ks * 8 + ka) * LDB + nb];
                uint32_t b1 = WB[(ks * 8 + 4 + ka) * LDB + nb];
                mma_tf32(accW[nt], a0, a1, a2, a3, b0, b1);
            }
        }
#pragma unroll
        for (int nt = 0; nt < 8; nt++) {
            int col = wn + nt * 8 + (ka << 1);
            float2 bb = *(const float2*)(be0 + col);
            As[(wm + lr) * LDA + col]         = f2tf(fmaxf(accW[nt][0] + bb.x, 0.f));
            As[(wm + lr) * LDA + col + 1]     = f2tf(fmaxf(accW[nt][1] + bb.y, 0.f));
            As[(wm + 8 + lr) * LDA + col]     = f2tf(fmaxf(accW[nt][2] + bb.x, 0.f));
            As[(wm + 8 + lr) * LDA + col + 1] = f2tf(fmaxf(accW[nt][3] + bb.y, 0.f));
        }
    } else {
#pragma unroll
        for (int i = 0; i < 8; i++) {
            int f = t + i * ETPB;
            int row = f >> 5, c4 = (f & 31) << 2;
            *(uint4*)(As + row * LDA + c4) = *(const uint4*)(g_e + (e0 + row) * HH + c4);
        }
    }

    float accM[8][4], accE[8][4];
#pragma unroll
    for (int i = 0; i < 8; i++)
#pragma unroll
        for (int j = 0; j < 4; j++) { accM[i][j] = 0.f; accE[i][j] = 0.f; }

#pragma unroll 1
    for (int kc = 0; kc < 4; kc++) {
        __syncthreads();
#pragma unroll
        for (int i = 0; i < 2; i++) {
            int ff = t + i * ETPB;
            int krow = ff >> 5, c4 = (ff & 31) << 2;
            if (ff < 32 * 32) {
                *(uint4*)(B1 + krow * LDB + c4) =
                    *(const uint4*)(wm3_t + (ll)(kc * 32 + krow) * HH + c4);
                if (do_edge)
                    *(uint4*)(B2 + krow * LDB + c4) =
                        *(const uint4*)(we_t + (ll)(kc * 32 + krow) * HH + c4);
            }
        }
        __syncthreads();
#pragma unroll
        for (int ks = 0; ks < 4; ks++) {
            int kb = kc * 32 + ks * 8 + ka;
            uint32_t a0 = As[(wm + lr) * LDA + kb];
            uint32_t a1 = As[(wm + 8 + lr) * LDA + kb];
            uint32_t a2 = As[(wm + lr) * LDA + kb + 4];
            uint32_t a3 = As[(wm + 8 + lr) * LDA + kb + 4];
#pragma unroll
            for (int nt = 0; nt < 8; nt++) {
                int nb = wn + nt * 8 + lr;
                uint32_t b0 = B1[(ks * 8 + ka) * LDB + nb];
                uint32_t b1 = B1[(ks * 8 + 4 + ka) * LDB + nb];
                mma_tf32(accM[nt], a0, a1, a2, a3, b0, b1);
            }
            if (do_edge) {
#pragma unroll
                for (int nt = 0; nt < 8; nt++) {
                    int nb = wn + nt * 8 + lr;
                    uint32_t b0 = B2[(ks * 8 + ka) * LDB + nb];
                    uint32_t b1 = B2[(ks * 8 + 4 + ka) * LDB + nb];
                    mma_tf32(accE[nt], a0, a1, a2, a3, b0, b1);
                }
            }
        }
    }

    // ---- merged epilogue: CsM aliases As, CsE aliases B region (+extra) ----
    __syncthreads();
#pragma unroll
    for (int nt = 0; nt < 8; nt++) {
        int col = wn + nt * 8 + (ka << 1);
        *(float2*)(CsM + (wm + lr) * LDA + col)     = make_float2(accM[nt][0], accM[nt][1]);
        *(float2*)(CsM + (wm + 8 + lr) * LDA + col) = make_float2(accM[nt][2], accM[nt][3]);
        if (do_edge) {
            *(float2*)(CsE + (wm + lr) * LDA + col)     = make_float2(accE[nt][0], accE[nt][1]);
            *(float2*)(CsE + (wm + 8 + lr) * LDA + col) = make_float2(accE[nt][2], accE[nt][3]);
        }
    }
    __syncthreads();
#pragma unroll
    for (int i = 0; i < 8; i++) {
        int f = t + i * ETPB;
        int row = f >> 5, c4 = (f & 31) << 2;
        int ge = (int)e0 + row;
        int d = dst[ge], s = src[ge];
        float4 cM = *(const float4*)(CsM + row * LDA + c4);
        float4 bb = *(const float4*)(bM + c4);
        float4 p1 = *(const float4*)(g_p1 + (ll)d * HH + c4);
        float4 p2 = *(const float4*)(g_p2 + (ll)s * HH + c4);
        if (do_edge) {
            // independent e-store overlaps the p1/p2 gather latency
            float4 cE  = *(const float4*)(CsE + row * LDA + c4);
            float4 bb2 = *(const float4*)(be + c4);
            uint4 u;
            u.x = f2tf(fmaxf(cE.x + bb2.x, 0.f));
            u.y = f2tf(fmaxf(cE.y + bb2.y, 0.f));
            u.z = f2tf(fmaxf(cE.z + bb2.z, 0.f));
            u.w = f2tf(fmaxf(cE.w + bb2.w, 0.f));
            *(uint4*)(g_e + (e0 + row) * HH + c4) = u;
        }
        float4 v;
        v.x = fmaxf(cM.x + bb.x + p1.x + p2.x, 0.f);
        v.y = fmaxf(cM.y + bb.y + p1.y + p2.y, 0.f);
        v.z = fmaxf(cM.z + bb.z + p1.z + p2.z, 0.f);
        v.w = fmaxf(cM.w + bb.w + p1.w + p2.w, 0.f);
        atomicAdd((float4*)(g_agg + (ll)d * HH + c4), v);
    }
}

// ---------------- fused update (3xBF16, BM=64) + agg zeroing ----------------
__global__ void __launch_bounds__(TPB) k_update_fused(int layer,
                                                      const float* __restrict__ bU,
                                                      const float* __restrict__ bn,
                                                      int has_next) {
    extern __shared__ uint32_t sm[];
    uint32_t* Ah  = sm + OFF_APH;
    uint32_t* Al  = sm + OFF_APL;
    uint32_t* B1h = sm + OFF_B1H;
    uint32_t* B1l = sm + OFF_B1L;
    uint32_t* B2h = sm + OFF_B2H;
    uint32_t* B2l = sm + OFF_B2L;
    float*    Cf  = (float*)(sm + OFF_CF);

    const uint32_t* wu_h = g_wu_h + layer * 128 * HH;
    const uint32_t* wu_l = g_wu_l + layer * 128 * HH;
    const uint32_t* wn_h = g_wn_h + layer * 64 * HH;
    const uint32_t* wn_l = g_wn_l + layer * 64 * HH;

    int t = threadIdx.x;
    int lane = t & 31, wid = t >> 5;
    int wm = (wid >> 1) << 4, wn = (wid & 1) << 6;
    int lr = lane >> 2, ka = lane & 3;
    int r = t >> 2, q = t & 3;
    int n0 = blockIdx.x * BM;
    int row = min(n0 + r, NN - 1);
    float rd = 1.f / fmaxf(g_deg[row], 1.f);

    float acc[8][4];
#pragma unroll
    for (int i = 0; i < 8; i++)
#pragma unroll
        for (int j = 0; j < 4; j++) acc[i][j] = 0.f;
#pragma unroll 1
    for (int c = 0; c < 8; c++) {
        __syncthreads();
        const float* p = (c < 4) ? (g_h + (ll)row * HH + c * 32)
                                 : (g_agg + (ll)row * HH + (c - 4) * 32);
        float sc = (c < 4) ? 1.f : rd;
        float4 v0 = *(const float4*)(p + q * 4);
        float4 v1 = *(const float4*)(p + 16 + q * 4);
        v0.x *= sc; v0.y *= sc; v0.z *= sc; v0.w *= sc;
        v1.x *= sc; v1.y *= sc; v1.z *= sc; v1.w *= sc;
        stage_Abf(Ah, Al, r, q, v0, v1);
        stage_Bpre(B1h, B1l, wu_h, wu_l, c * 16);
        __syncthreads();
        mma3_bf(Ah, Al, B1h, B1l, wm, wn, lr, ka, acc);
    }
    frag_relu_toCf(Cf, acc, bU, wm, wn, lr, ka);

    {
        float4 z = make_float4(0.f, 0.f, 0.f, 0.f);
#pragma unroll
        for (int i = 0; i < 8; i++) {
            int f = t + i * TPB;
            int rr = n0 + (f >> 5);
            if (rr < NN)
                *(float4*)(g_agg + (ll)rr * HH + ((f & 31) << 2)) = z;
        }
    }

#pragma unroll
    for (int i = 0; i < 8; i++)
#pragma unroll
        for (int j = 0; j < 4; j++) acc[i][j] = 0.f;
#pragma unroll 1
    for (int kc = 0; kc < 4; kc++) {
        __syncthreads();
        stage_Abf_fromCf(Ah, Al, Cf, kc);
        stage_Bpre(B1h, B1l, wn_h, wn_l, kc * 16);
        __syncthreads();
        mma3_bf(Ah, Al, B1h, B1l, wm, wn, lr, ka, acc);
    }
    __syncthreads();
    frag_relu_toCf(Cf, acc, bn, wm, wn, lr, ka);
    __syncthreads();
#pragma unroll
    for (int i = 0; i < 8; i++) {
        int f = t + i * TPB;
        int rr = f >> 5, c4 = (f & 31) << 2;
        int gr = n0 + rr;
        if (gr < NN)
            *(float4*)(g_h + (ll)gr * HH + c4) = *(const float4*)(Cf + rr * LDA + c4);
    }

    if (has_next)
        p_passes(Ah, Al, B1h, B1l, B2h, B2l, Cf, layer + 1, n0, wm, wn, lr, ka);
}

// ---------------- global mean pool ----------------
__global__ void k_pool(const int* __restrict__ bvec) {
    int t = blockIdx.x * blockDim.x + threadIdx.x;
    int c4 = (t & 31) << 2;
    int nb = (t >> 5) * 16;
    if (nb >= NN) return;
    int end = min(nb + 16, NN);
    int g = bvec[nb];
    float4 s = make_float4(0.f, 0.f, 0.f, 0.f);
    float cnt = 0.f;
    for (int n = nb; n < end; n++) {
        int gn = bvec[n];
        if (gn != g) {
            atomicAdd((float4*)(g_pool + g * HH + c4), s);
            if (c4 == 0) atomicAdd(&g_cnt[g], cnt);
            s = make_float4(0.f, 0.f, 0.f, 0.f);
            cnt = 0.f;
            g = gn;
        }
        float4 hv = *(const float4*)(g_h + (ll)n * HH + c4);
        s.x += hv.x; s.y += hv.y; s.z += hv.z; s.w += hv.w;
        cnt += 1.f;
    }
    atomicAdd((float4*)(g_pool + g * HH + c4), s);
    if (c4 == 0) atomicAdd(&g_cnt[g], cnt);
}

__global__ void k_head(const float* __restrict__ Wh, const float* __restrict__ bh,
                       float* __restrict__ out) {
    int g = threadIdx.x;
    float rc = 1.f / fmaxf(g_cnt[g], 1.f);
    float acc = bh[0];
#pragma unroll
    for (int k = 0; k < HH; k++)
        acc += g_pool[g * HH + k] * rc * Wh[k];
    out[g] = acc;
}

// ---------------- launch ----------------
extern "C" void kernel_launch(void* const* d_in, const int* in_sizes, int n_in,
                              void* d_out, int out_size) {
    const float* x    = (const float*)d_in[0];
    const int*   ei   = (const int*)d_in[1];
    const float* ea   = (const float*)d_in[2];
    const int*   bvec = (const int*)d_in[3];
    const float* Wn0  = (const float*)d_in[4];
    const float* bn0  = (const float*)d_in[5];
    const float* We0  = (const float*)d_in[6];
    const float* be0  = (const float*)d_in[7];
    const float* WM   = (const float*)d_in[8];
    const float* bM   = (const float*)d_in[9];
    const float* WU   = (const float*)d_in[10];
    const float* bU   = (const float*)d_in[11];
    const float* Wn   = (const float*)d_in[12];
    const float* bn   = (const float*)d_in[13];
    const float* We   = (const float*)d_in[14];
    const float* be   = (const float*)d_in[15];
    const float* Wh   = (const float*)d_in[16];
    const float* bh   = (const float*)d_in[17];
    float* out = (float*)d_out;

    const int* src = ei;
    const int* dst = ei + EE;

    static int attr_done = 0;
    if (!attr_done) {
        cudaFuncSetAttribute(k_edge_tf32, cudaFuncAttributeMaxDynamicSharedMemorySize,
                             EDGE_SMEM);
        cudaFuncSetAttribute(k_enc_fused, cudaFuncAttributeMaxDynamicSharedMemorySize,
                             NODE_SMEM);
        cudaFuncSetAttribute(k_update_fused, cudaFuncAttributeMaxDynamicSharedMemorySize,
                             NODE_SMEM);
        attr_done = 1;
    }

    int prep_threads = 3 * 40960 + 2 * 3 * 16384 + 16 * HH + NN;
    k_prep<<<(prep_threads + 255) / 256, 256>>>(WM, WU, Wn, We, We0);

    k_deg<<<(EE + 255) / 256, 256>>>(dst);

    int nblk = (NN + BM - 1) / BM;
    k_enc_fused<<<nblk, TPB, NODE_SMEM>>>(x, Wn0, bn0);

    for (int l = 0; l < 3; l++) {
        k_edge_tf32<<<EE / EBM, ETPB, EDGE_SMEM>>>(src, dst, l, bM + l * HH,
                                                   be + l * HH, ea, be0,
                                                   l < 2 ? 1 : 0);
        k_update_fused<<<nblk, TPB, NODE_SMEM>>>(l, bU + l * HH, bn + l * HH,
                                                 l < 2 ? 1 : 0);
    }

    int pool_threads = ((NN + 15) / 16) * 32;
    k_pool<<<(pool_threads + 255) / 256, 256>>>(bvec);
    k_head<<<1, GG>>>(Wh, bh, out);
}

// round 17
// speedup vs baseline: 1.3998x; 1.0362x over previous
#include <cuda_runtime.h>
#include <cstdint>

#define NN 100000
#define EE 640000
#define GG 256
#define HH 128
#define TPB 256
#define BM 64
#define EBM 128
#define ETPB 512
#define LDA 132
#define LDB 136
#define LDAS 36
#define LDAP 20
#define LDBP 136

typedef long long ll;

// ---------------- scratch ----------------
__device__ float g_h[NN * HH];
__device__ float g_agg[NN * HH];
__device__ float g_p1[NN * HH];
__device__ float g_p2[NN * HH];
__device__ uint32_t g_e[(ll)EE * HH];     // e stored as tf32 bit patterns
__device__ float g_deg[NN];
__device__ float g_pool[GG * HH];
__device__ float g_cnt[GG];

// pre-converted weights
__device__ uint32_t g_wu_h[3 * 128 * HH],   g_wu_l[3 * 128 * HH];
__device__ uint32_t g_wn_h[3 * 64 * HH],    g_wn_l[3 * 64 * HH];
__device__ uint32_t g_wm12_h[3 * 128 * HH], g_wm12_l[3 * 128 * HH];
__device__ uint32_t g_wm3_t[3 * 128 * HH];
__device__ uint32_t g_we_t[3 * 128 * HH];
__device__ uint32_t g_we0_t[16 * HH];

// ---------------- helpers ----------------
__device__ __forceinline__ uint32_t f2tf(float f) {
    uint32_t u;
    asm("cvt.rna.tf32.f32 %0, %1;" : "=r"(u) : "f"(f));
    return u;
}
__device__ __forceinline__ void mma_tf32(float* c, uint32_t a0, uint32_t a1,
                                         uint32_t a2, uint32_t a3,
                                         uint32_t b0, uint32_t b1) {
    asm volatile(
        "mma.sync.aligned.m16n8k8.row.col.f32.tf32.tf32.f32 "
        "{%0,%1,%2,%3}, {%4,%5,%6,%7}, {%8,%9}, {%0,%1,%2,%3};\n"
        : "+f"(c[0]), "+f"(c[1]), "+f"(c[2]), "+f"(c[3])
        : "r"(a0), "r"(a1), "r"(a2), "r"(a3), "r"(b0), "r"(b1));
}
__device__ __forceinline__ void split_pack(float v0, float v1,
                                           uint32_t& ph, uint32_t& pl) {
    uint32_t h;
    asm("cvt.rn.bf16x2.f32 %0, %1, %2;" : "=r"(h) : "f"(v1), "f"(v0));
    float h0 = __uint_as_float(h << 16);
    float h1 = __uint_as_float(h & 0xffff0000u);
    asm("cvt.rn.bf16x2.f32 %0, %1, %2;" : "=r"(pl) : "f"(v1 - h1), "f"(v0 - h0));
    ph = h;
}
__device__ __forceinline__ void mma_bf16(float* c, uint32_t a0, uint32_t a1,
                                         uint32_t a2, uint32_t a3,
                                         uint32_t b0, uint32_t b1) {
    asm volatile(
        "mma.sync.aligned.m16n8k16.row.col.f32.bf16.bf16.f32 "
        "{%0,%1,%2,%3}, {%4,%5,%6,%7}, {%8,%9}, {%0,%1,%2,%3};\n"
        : "+f"(c[0]), "+f"(c[1]), "+f"(c[2]), "+f"(c[3])
        : "r"(a0), "r"(a1), "r"(a2), "r"(a3), "r"(b0), "r"(b1));
}

// ---------------- weight prep + misc zero (one launch) ----------------
__global__ void k_prep(const float* __restrict__ WM, const float* __restrict__ WU,
                       const float* __restrict__ Wn, const float* __restrict__ We,
                       const float* __restrict__ We0) {
    int i = blockIdx.x * blockDim.x + threadIdx.x;
    if (i < 3 * 40960) {
        int l = i / 40960, j = i % 40960;
        const float* W;
        uint32_t *dh, *dl;
        if (j < 16384)      { W = WU + (ll)l * 256 * HH; dh = g_wu_h + l * 16384;  dl = g_wu_l + l * 16384; }
        else if (j < 24576) { j -= 16384; W = Wn + (ll)l * 128 * HH; dh = g_wn_h + l * 8192; dl = g_wn_l + l * 8192; }
        else                { j -= 24576; W = WM + (ll)l * 384 * HH; dh = g_wm12_h + l * 16384; dl = g_wm12_l + l * 16384; }
        int kp = j >> 7, n = j & 127;
        uint32_t h, lo;
        split_pack(W[(ll)(2 * kp) * HH + n], W[(ll)(2 * kp + 1) * HH + n], h, lo);
        dh[j] = h; dl[j] = lo;
    } else {
        int k = i - 3 * 40960;
        if (k < 3 * 16384) {
            int l = k / 16384, j = k % 16384;
            g_wm3_t[k] = f2tf(WM[(ll)l * 384 * HH + 256 * HH + j]);
        } else {
            k -= 3 * 16384;
            if (k < 3 * 16384) {
                g_we_t[k] = f2tf(We[k]);
            } else {
                k -= 3 * 16384;
                if (k < 16 * HH) {
                    g_we0_t[k] = f2tf(We0[k]);
                } else {
                    k -= 16 * HH;
                    if (k < NN) g_deg[k] = 0.f;
                    if (k < GG * HH) g_pool[k] = 0.f;
                    if (k < GG) g_cnt[k] = 0.f;
                }
            }
        }
    }
}

// ---------------- node-kernel smem partition (BM=64) ----------------
#define OFF_APH 0
#define OFF_APL (BM * LDAP)
#define OFF_B1H (2 * BM * LDAP)
#define OFF_B1L (OFF_B1H + 16 * LDBP)
#define OFF_B2H (OFF_B1H + 2 * 16 * LDBP)
#define OFF_B2L (OFF_B1H + 3 * 16 * LDBP)
#define OFF_CF  (OFF_B1H + 4 * 16 * LDBP)
#define NODE_SMEM ((OFF_CF + BM * LDA) * 4)

__device__ __forceinline__ void stage_Bpre(uint32_t* Bh, uint32_t* Bl,
                                           const uint32_t* __restrict__ GH,
                                           const uint32_t* __restrict__ GL, int kp0) {
    int t = threadIdx.x;
#pragma unroll
    for (int i = 0; i < 2; i++) {
        int f = t + i * TPB;
        int kp = f >> 5, n = (f & 31) << 2;
        *(uint4*)(Bh + kp * LDBP + n) = *(const uint4*)(GH + (ll)(kp0 + kp) * HH + n);
        *(uint4*)(Bl + kp * LDBP + n) = *(const uint4*)(GL + (ll)(kp0 + kp) * HH + n);
    }
}

__device__ __forceinline__ void stage_Abf(uint32_t* Ah, uint32_t* Al,
                                          int r, int q, float4 v0, float4 v1) {
    uint32_t h0, l0, h1, l1;
    split_pack(v0.x, v0.y, h0, l0);
    split_pack(v0.z, v0.w, h1, l1);
    *(uint2*)(Ah + r * LDAP + 2 * q) = make_uint2(h0, h1);
    *(uint2*)(Al + r * LDAP + 2 * q) = make_uint2(l0, l1);
    split_pack(v1.x, v1.y, h0, l0);
    split_pack(v1.z, v1.w, h1, l1);
    *(uint2*)(Ah + r * LDAP + 8 + 2 * q) = make_uint2(h0, h1);
    *(uint2*)(Al + r * LDAP + 8 + 2 * q) = make_uint2(l0, l1);
}

__device__ __forceinline__ void stage_Abf_fromCf(uint32_t* Ah, uint32_t* Al,
                                                 const float* Cf, int kc) {
    int t = threadIdx.x;
    int r = t >> 2, q = t & 3;
    float4 v0 = *(const float4*)(Cf + r * LDA + kc * 32 + q * 4);
    float4 v1 = *(const float4*)(Cf + r * LDA + kc * 32 + 16 + q * 4);
    stage_Abf(Ah, Al, r, q, v0, v1);
}

__device__ __forceinline__ void mma3_bf(const uint32_t* Ah, const uint32_t* Al,
                                        const uint32_t* Bh, const uint32_t* Bl,
                                        int wm, int wn, int lr, int ka,
                                        float acc[8][4]) {
#pragma unroll
    for (int ks = 0; ks < 2; ks++) {
        int kpb = ks * 8;
        uint32_t ah0 = Ah[(wm + lr) * LDAP + kpb + ka];
        uint32_t ah1 = Ah[(wm + 8 + lr) * LDAP + kpb + ka];
        uint32_t ah2 = Ah[(wm + lr) * LDAP + kpb + ka + 4];
        uint32_t ah3 = Ah[(wm + 8 + lr) * LDAP + kpb + ka + 4];
        uint32_t al0 = Al[(wm + lr) * LDAP + kpb + ka];
        uint32_t al1 = Al[(wm + 8 + lr) * LDAP + kpb + ka];
        uint32_t al2 = Al[(wm + lr) * LDAP + kpb + ka + 4];
        uint32_t al3 = Al[(wm + 8 + lr) * LDAP + kpb + ka + 4];
#pragma unroll
        for (int nt = 0; nt < 8; nt++) {
            int nb = wn + nt * 8 + lr;
            uint32_t bh0 = Bh[(kpb + ka) * LDBP + nb];
            uint32_t bh1 = Bh[(kpb + ka + 4) * LDBP + nb];
            uint32_t bl0 = Bl[(kpb + ka) * LDBP + nb];
            uint32_t bl1 = Bl[(kpb + ka + 4) * LDBP + nb];
            mma_bf16(acc[nt], ah0, ah1, ah2, ah3, bh0, bh1);
            mma_bf16(acc[nt], al0, al1, al2, al3, bh0, bh1);
            mma_bf16(acc[nt], ah0, ah1, ah2, ah3, bl0, bl1);
        }
    }
}

__device__ __forceinline__ void mma3_bf_dual(const uint32_t* Ah, const uint32_t* Al,
                                             const uint32_t* B1h, const uint32_t* B1l,
                                             const uint32_t* B2h, const uint32_t* B2l,
                                             int wm, int wn, int lr, int ka,
                                             float accA[8][4], float accB[8][4]) {
#pragma unroll
    for (int ks = 0; ks < 2; ks++) {
        int kpb = ks * 8;
        uint32_t ah0 = Ah[(wm + lr) * LDAP + kpb + ka];
        uint32_t ah1 = Ah[(wm + 8 + lr) * LDAP + kpb + ka];
        uint32_t ah2 = Ah[(wm + lr) * LDAP + kpb + ka + 4];
        uint32_t ah3 = Ah[(wm + 8 + lr) * LDAP + kpb + ka + 4];
        uint32_t al0 = Al[(wm + lr) * LDAP + kpb + ka];
        uint32_t al1 = Al[(wm + 8 + lr) * LDAP + kpb + ka];
        uint32_t al2 = Al[(wm + lr) * LDAP + kpb + ka + 4];
        uint32_t al3 = Al[(wm + 8 + lr) * LDAP + kpb + ka + 4];
#pragma unroll
        for (int nt = 0; nt < 8; nt++) {
            int nb = wn + nt * 8 + lr;
            uint32_t bh0 = B1h[(kpb + ka) * LDBP + nb];
            uint32_t bh1 = B1h[(kpb + ka + 4) * LDBP + nb];
            uint32_t bl0 = B1l[(kpb + ka) * LDBP + nb];
            uint32_t bl1 = B1l[(kpb + ka + 4) * LDBP + nb];
            mma_bf16(accA[nt], ah0, ah1, ah2, ah3, bh0, bh1);
            mma_bf16(accA[nt], al0, al1, al2, al3, bh0, bh1);
            mma_bf16(accA[nt], ah0, ah1, ah2, ah3, bl0, bl1);
            bh0 = B2h[(kpb + ka) * LDBP + nb];
            bh1 = B2h[(kpb + ka + 4) * LDBP + nb];
            bl0 = B2l[(kpb + ka) * LDBP + nb];
            bl1 = B2l[(kpb + ka + 4) * LDBP + nb];
            mma_bf16(accB[nt], ah0, ah1, ah2, ah3, bh0, bh1);
            mma_bf16(accB[nt], al0, al1, al2, al3, bh0, bh1);
            mma_bf16(accB[nt], ah0, ah1, ah2, ah3, bl0, bl1);
        }
    }
}

__device__ __forceinline__ void frag_relu_toCf(float* Cf, const float acc[8][4],
                                               const float* __restrict__ bias,
                                               int wm, int wn, int lr, int ka) {
#pragma unroll
    for (int nt = 0; nt < 8; nt++) {
        int col = wn + nt * 8 + (ka << 1);
        float2 bb = *(const float2*)(bias + col);
        Cf[(wm + lr) * LDA + col]         = fmaxf(acc[nt][0] + bb.x, 0.f);
        Cf[(wm + lr) * LDA + col + 1]     = fmaxf(acc[nt][1] + bb.y, 0.f);
        Cf[(wm + 8 + lr) * LDA + col]     = fmaxf(acc[nt][2] + bb.x, 0.f);
        Cf[(wm + 8 + lr) * LDA + col + 1] = fmaxf(acc[nt][3] + bb.y, 0.f);
    }
}

__device__ __forceinline__ void p_passes(uint32_t* Ah, uint32_t* Al,
                                         uint32_t* B1h, uint32_t* B1l,
                                         uint32_t* B2h, uint32_t* B2l, float* Cf,
                                         int layer,
                                         int n0, int wm, int wn, int lr, int ka) {
    const uint32_t* GH1 = g_wm12_h + layer * 128 * HH;
    const uint32_t* GL1 = g_wm12_l + layer * 128 * HH;
    const uint32_t* GH2 = GH1 + 64 * HH;
    const uint32_t* GL2 = GL1 + 64 * HH;
    float accA[8][4], accB[8][4];
#pragma unroll
    for (int i = 0; i < 8; i++)
#pragma unroll
        for (int j = 0; j < 4; j++) { accA[i][j] = 0.f; accB[i][j] = 0.f; }
#pragma unroll 1
    for (int kc = 0; kc < 4; kc++) {
        __syncthreads();
        stage_Abf_fromCf(Ah, Al, Cf, kc);
        stage_Bpre(B1h, B1l, GH1, GL1, kc * 16);
        stage_Bpre(B2h, B2l, GH2, GL2, kc * 16);
        __syncthreads();
        mma3_bf_dual(Ah, Al, B1h, B1l, B2h, B2l, wm, wn, lr, ka, accA, accB);
    }
    int row0 = n0 + wm + lr, row1 = row0 + 8;
#pragma unroll
    for (int nt = 0; nt < 8; nt++) {
        int col = wn + nt * 8 + (ka << 1);
        if (row0 < NN) {
            *(float2*)(g_p1 + (ll)row0 * HH + col) = make_float2(accA[nt][0], accA[nt][1]);
            *(float2*)(g_p2 + (ll)row0 * HH + col) = make_float2(accB[nt][0], accB[nt][1]);
        }
        if (row1 < NN) {
            *(float2*)(g_p1 + (ll)row1 * HH + col) = make_float2(accA[nt][2], accA[nt][3]);
            *(float2*)(g_p2 + (ll)row1 * HH + col) = make_float2(accB[nt][2], accB[nt][3]);
        }
    }
}

// ---------------- fp32 helpers (node encoder) ----------------
template<int KC>
__device__ __forceinline__ void load_B(float* Bs, const float* __restrict__ W, int k0) {
    int t = threadIdx.x;
#pragma unroll
    for (int i = 0; i < (KC * HH / 4) / TPB; i++) {
        int f = t + i * TPB;
        int k = f >> 5;
        int c = (f & 31) << 2;
        *(float4*)(Bs + k * HH + c) = *(const float4*)(W + (ll)(k0 + k) * HH + c);
    }
}

template<int KB, int LA>
__device__ __forceinline__ void mma8x4(const float* __restrict__ As,
                                       const float* __restrict__ Bs,
                                       int tr8, int tc4, float acc[8][4]) {
#pragma unroll
    for (int kb = 0; kb < KB; kb++) {
        float4 b0 = *(const float4*)(Bs + (kb * 4 + 0) * HH + tc4);
        float4 b1 = *(const float4*)(Bs + (kb * 4 + 1) * HH + tc4);
        float4 b2 = *(const float4*)(Bs + (kb * 4 + 2) * HH + tc4);
        float4 b3 = *(const float4*)(Bs + (kb * 4 + 3) * HH + tc4);
#pragma unroll
        for (int i = 0; i < 8; i++) {
            float4 a = *(const float4*)(As + (tr8 + i) * LA + kb * 4);
            acc[i][0] += a.x * b0.x; acc[i][1] += a.x * b0.y; acc[i][2] += a.x * b0.z; acc[i][3] += a.x * b0.w;
            acc[i][0] += a.y * b1.x; acc[i][1] += a.y * b1.y; acc[i][2] += a.y * b1.z; acc[i][3] += a.y * b1.w;
            acc[i][0] += a.z * b2.x; acc[i][1] += a.z * b2.y; acc[i][2] += a.z * b2.z; acc[i][3] += a.z * b2.w;
            acc[i][0] += a.w * b3.x; acc[i][1] += a.w * b3.y; acc[i][2] += a.w * b3.z; acc[i][3] += a.w * b3.w;
        }
    }
}

__device__ __forceinline__ float4 relu4(const float acc[4], float4 b) {
    float4 v;
    v.x = fmaxf(acc[0] + b.x, 0.f);
    v.y = fmaxf(acc[1] + b.y, 0.f);
    v.z = fmaxf(acc[2] + b.z, 0.f);
    v.w = fmaxf(acc[3] + b.w, 0.f);
    return v;
}

// ---------------- degree ----------------
__global__ void k_deg(const int* __restrict__ dst) {
    int e = blockIdx.x * blockDim.x + threadIdx.x;
    if (e < EE) atomicAdd(&g_deg[dst[e]], 1.f);
}

// ---------------- fused node encoder (+ agg zero for layer 0) ----------------
__global__ void __launch_bounds__(TPB) k_enc_fused(const float* __restrict__ x,
                                                   const float* __restrict__ W,
                                                   const float* __restrict__ b) {
    extern __shared__ uint32_t sm[];
    uint32_t* Ah  = sm + OFF_APH;
    uint32_t* Al  = sm + OFF_APL;
    uint32_t* B1h = sm + OFF_B1H;
    uint32_t* B1l = sm + OFF_B1L;
    uint32_t* B2h = sm + OFF_B2H;
    uint32_t* B2l = sm + OFF_B2L;
    float*    Cf  = (float*)(sm + OFF_CF);
    float*    As  = (float*)Ah;
    float*    Bs  = (float*)B1h;

    int t = threadIdx.x;
    int lane = t & 31, wid = t >> 5;
    int wm = (wid >> 1) << 4, wn = (wid & 1) << 6;
    int lr = lane >> 2, ka = lane & 3;
    int tr8 = (t >> 5) << 3, tc4 = (t & 31) << 2;
    int r = t >> 2, q = t & 3;
    int n0 = blockIdx.x * BM;
    int row = min(n0 + r, NN - 1);

    float4 z = make_float4(0.f, 0.f, 0.f, 0.f);
#pragma unroll
    for (int i = 0; i < 8; i++) {
        int f = t + i * TPB;
        int rr = n0 + (f >> 5);
        if (rr < NN)
            *(float4*)(g_agg + (ll)rr * HH + ((f & 31) << 2)) = z;
    }

    float acc[8][4] = {};
#pragma unroll 1
    for (int c = 0; c < 2; c++) {
        __syncthreads();
        const float* p = x + (ll)row * 64 + c * 32;
        *(float4*)(As + r * LDAS + q * 4)      = *(const float4*)(p + q * 4);
        *(float4*)(As + r * LDAS + 16 + q * 4) = *(const float4*)(p + 16 + q * 4);
        load_B<32>(Bs, W, c * 32);
        __syncthreads();
        mma8x4<8, LDAS>(As, Bs, tr8, tc4, acc);
    }
    __syncthreads();
    float4 bb = *(const float4*)(b + tc4);
#pragma unroll
    for (int i = 0; i < 8; i++) {
        float4 v = relu4(acc[i], bb);
        int rr = n0 + tr8 + i;
        *(float4*)(Cf + (tr8 + i) * LDA + tc4) = v;
        if (rr < NN)
            *(float4*)(g_h + (ll)rr * HH + tc4) = v;
    }
    p_passes(Ah, Al, B1h, B1l, B2h, B2l, Cf, 0, n0, wm, wn, lr, ka);
}

// ---------------- tf32 fused edge kernel: reg-prefetch double-buffered B ----------------
// smem: As 128*LDA | Bbuf 2 x (2*32*LDB) ; CsM aliases As, CsE aliases Bbuf (17408 >= 16896)
#define BSTG2 (2 * 32 * LDB)
#define EDGE_SMEM ((EBM * LDA + 2 * BSTG2) * 4)
__global__ void __launch_bounds__(ETPB) k_edge_tf32(const int* __restrict__ src,
                                                    const int* __restrict__ dst,
                                                    int layer,
                                                    const float* __restrict__ bM,
                                                    const float* __restrict__ be,
                                                    const float* __restrict__ ea,
                                                    const float* __restrict__ be0,
                                                    int do_edge) {
    extern __shared__ uint32_t smem_u[];
    uint32_t* As = smem_u;
    uint32_t* Bbuf = smem_u + EBM * LDA;
    float*    CsM = (float*)As;
    float*    CsE = (float*)Bbuf;

    const uint32_t* wm3_t = g_wm3_t + layer * 128 * HH;
    const uint32_t* we_t  = g_we_t  + layer * 128 * HH;

    int t = threadIdx.x;
    int lane = t & 31, wid = t >> 5;
    int wm = (wid >> 1) << 4;
    int wn = (wid & 1) << 6;
    int lr = lane >> 2, ka = lane & 3;
    ll e0 = (ll)blockIdx.x * EBM;

    // per-thread B staging coordinates (two fragments of 16B each per matrix)
    int krow0 = t >> 5,            c40 = (t & 31) << 2;
    int krow1 = (t + ETPB) >> 5,   c41 = ((t + ETPB) & 31) << 2;

    // prefetch chunk 0 into registers
    uint4 rb1a = *(const uint4*)(wm3_t + (ll)krow0 * HH + c40);
    uint4 rb1b = *(const uint4*)(wm3_t + (ll)krow1 * HH + c41);
    uint4 rb2a, rb2b;
    if (do_edge) {
        rb2a = *(const uint4*)(we_t + (ll)krow0 * HH + c40);
        rb2b = *(const uint4*)(we_t + (ll)krow1 * HH + c41);
    }

    // ---- A stage ----
    if (layer == 0) {
        // in-tile edge encoder: As = tf32(relu(ea @ We0 + be0)); scratch in Bbuf
        uint32_t* EA = Bbuf;
        uint32_t* WB = Bbuf + 128 * LDAP;
        {
            int rr = t >> 2, qq = t & 3;
            float4 v = *(const float4*)(ea + (e0 + rr) * 16 + qq * 4);
            uint4 u;
            u.x = f2tf(v.x); u.y = f2tf(v.y); u.z = f2tf(v.z); u.w = f2tf(v.w);
            *(uint4*)(EA + rr * LDAP + qq * 4) = u;
        }
        {
            int krow = t >> 5, c4 = (t & 31) << 2;
            *(uint4*)(WB + krow * LDB + c4) = *(const uint4*)(g_we0_t + krow * HH + c4);
        }
        __syncthreads();
        float accW[8][4] = {};
#pragma unroll
        for (int ks = 0; ks < 2; ks++) {
            int kb = ks * 8 + ka;
            uint32_t a0 = EA[(wm + lr) * LDAP + kb];
            uint32_t a1 = EA[(wm + 8 + lr) * LDAP + kb];
            uint32_t a2 = EA[(wm + lr) * LDAP + kb + 4];
            uint32_t a3 = EA[(wm + 8 + lr) * LDAP + kb + 4];
#pragma unroll
            for (int nt = 0; nt < 8; nt++) {
                int nb = wn + nt * 8 + lr;
                uint32_t b0 = WB[(ks * 8 + ka) * LDB + nb];
                uint32_t b1 = WB[(ks * 8 + 4 + ka) * LDB + nb];
                mma_tf32(accW[nt], a0, a1, a2, a3, b0, b1);
            }
        }
#pragma unroll
        for (int nt = 0; nt < 8; nt++) {
            int col = wn + nt * 8 + (ka << 1);
            float2 bb = *(const float2*)(be0 + col);
            As[(wm + lr) * LDA + col]         = f2tf(fmaxf(accW[nt][0] + bb.x, 0.f));
            As[(wm + lr) * LDA + col + 1]     = f2tf(fmaxf(accW[nt][1] + bb.y, 0.f));
            As[(wm + 8 + lr) * LDA + col]     = f2tf(fmaxf(accW[nt][2] + bb.x, 0.f));
            As[(wm + 8 + lr) * LDA + col + 1] = f2tf(fmaxf(accW[nt][3] + bb.y, 0.f));
        }
    } else {
#pragma unroll
        for (int i = 0; i < 8; i++) {
            int f = t + i * ETPB;
            int row = f >> 5, c4 = (f & 31) << 2;
            *(uint4*)(As + row * LDA + c4) = *(const uint4*)(g_e + (e0 + row) * HH + c4);
        }
    }
    __syncthreads();   // A-stage (and layer-0 Bbuf scratch reads) complete before STS(0)

    float accM[8][4], accE[8][4];
#pragma unroll
    for (int i = 0; i < 8; i++)
#pragma unroll
        for (int j = 0; j < 4; j++) { accM[i][j] = 0.f; accE[i][j] = 0.f; }

    // ---- pipelined mainloop: STS(kc) -> LDG(kc+1) -> sync -> mma(kc) ----
#pragma unroll
    for (int kc = 0; kc < 4; kc++) {
        uint32_t* Bc1 = Bbuf + (kc & 1) * BSTG2;
        uint32_t* Bc2 = Bc1 + 32 * LDB;
        *(uint4*)(Bc1 + krow0 * LDB + c40) = rb1a;
        *(uint4*)(Bc1 + krow1 * LDB + c41) = rb1b;
        if (do_edge) {
            *(uint4*)(Bc2 + krow0 * LDB + c40) = rb2a;
            *(uint4*)(Bc2 + krow1 * LDB + c41) = rb2b;
        }
        if (kc < 3) {
            rb1a = *(const uint4*)(wm3_t + (ll)((kc + 1) * 32 + krow0) * HH + c40);
            rb1b = *(const uint4*)(wm3_t + (ll)((kc + 1) * 32 + krow1) * HH + c41);
            if (do_edge) {
                rb2a = *(const uint4*)(we_t + (ll)((kc + 1) * 32 + krow0) * HH + c40);
                rb2b = *(const uint4*)(we_t + (ll)((kc + 1) * 32 + krow1) * HH + c41);
            }
        }
        __syncthreads();
#pragma unroll
        for (int ks = 0; ks < 4; ks++) {
            int kb = kc * 32 + ks * 8 + ka;
            uint32_t a0 = As[(wm + lr) * LDA + kb];
            uint32_t a1 = As[(wm + 8 + lr) * LDA + kb];
            uint32_t a2 = As[(wm + lr) * LDA + kb + 4];
            uint32_t a3 = As[(wm + 8 + lr) * LDA + kb + 4];
#pragma unroll
            for (int nt = 0; nt < 8; nt++) {
                int nb = wn + nt * 8 + lr;
                uint32_t b0 = Bc1[(ks * 8 + ka) * LDB + nb];
                uint32_t b1 = Bc1[(ks * 8 + 4 + ka) * LDB + nb];
                mma_tf32(accM[nt], a0, a1, a2, a3, b0, b1);
            }
            if (do_edge) {
#pragma unroll
                for (int nt = 0; nt < 8; nt++) {
                    int nb = wn + nt * 8 + lr;
                    uint32_t b0 = Bc2[(ks * 8 + ka) * LDB + nb];
                    uint32_t b1 = Bc2[(ks * 8 + 4 + ka) * LDB + nb];
                    mma_tf32(accE[nt], a0, a1, a2, a3, b0, b1);
                }
            }
        }
    }

    // ---- merged epilogue: CsM aliases As, CsE aliases Bbuf ----
    __syncthreads();
#pragma unroll
    for (int nt = 0; nt < 8; nt++) {
        int col = wn + nt * 8 + (ka << 1);
        *(float2*)(CsM + (wm + lr) * LDA + col)     = make_float2(accM[nt][0], accM[nt][1]);
        *(float2*)(CsM + (wm + 8 + lr) * LDA + col) = make_float2(accM[nt][2], accM[nt][3]);
        if (do_edge) {
            *(float2*)(CsE + (wm + lr) * LDA + col)     = make_float2(accE[nt][0], accE[nt][1]);
            *(float2*)(CsE + (wm + 8 + lr) * LDA + col) = make_float2(accE[nt][2], accE[nt][3]);
        }
    }
    __syncthreads();
#pragma unroll
    for (int i = 0; i < 8; i++) {
        int f = t + i * ETPB;
        int row = f >> 5, c4 = (f & 31) << 2;
        int ge = (int)e0 + row;
        int d = dst[ge], s = src[ge];
        float4 cM = *(const float4*)(CsM + row * LDA + c4);
        float4 bb = *(const float4*)(bM + c4);
        float4 p1 = *(const float4*)(g_p1 + (ll)d * HH + c4);
        float4 p2 = *(const float4*)(g_p2 + (ll)s * HH + c4);
        if (do_edge) {
            float4 cE  = *(const float4*)(CsE + row * LDA + c4);
            float4 bb2 = *(const float4*)(be + c4);
            uint4 u;
            u.x = f2tf(fmaxf(cE.x + bb2.x, 0.f));
            u.y = f2tf(fmaxf(cE.y + bb2.y, 0.f));
            u.z = f2tf(fmaxf(cE.z + bb2.z, 0.f));
            u.w = f2tf(fmaxf(cE.w + bb2.w, 0.f));
            *(uint4*)(g_e + (e0 + row) * HH + c4) = u;
        }
        float4 v;
        v.x = fmaxf(cM.x + bb.x + p1.x + p2.x, 0.f);
        v.y = fmaxf(cM.y + bb.y + p1.y + p2.y, 0.f);
        v.z = fmaxf(cM.z + bb.z + p1.z + p2.z, 0.f);
        v.w = fmaxf(cM.w + bb.w + p1.w + p2.w, 0.f);
        atomicAdd((float4*)(g_agg + (ll)d * HH + c4), v);
    }
}

// ---------------- fused update (3xBF16, BM=64) + agg zeroing ----------------
__global__ void __launch_bounds__(TPB) k_update_fused(int layer,
                                                      const float* __restrict__ bU,
                                                      const float* __restrict__ bn,
                                                      int has_next) {
    extern __shared__ uint32_t sm[];
    uint32_t* Ah  = sm + OFF_APH;
    uint32_t* Al  = sm + OFF_APL;
    uint32_t* B1h = sm + OFF_B1H;
    uint32_t* B1l = sm + OFF_B1L;
    uint32_t* B2h = sm + OFF_B2H;
    uint32_t* B2l = sm + OFF_B2L;
    float*    Cf  = (float*)(sm + OFF_CF);

    const uint32_t* wu_h = g_wu_h + layer * 128 * HH;
    const uint32_t* wu_l = g_wu_l + layer * 128 * HH;
    const uint32_t* wn_h = g_wn_h + layer * 64 * HH;
    const uint32_t* wn_l = g_wn_l + layer * 64 * HH;

    int t = threadIdx.x;
    int lane = t & 31, wid = t >> 5;
    int wm = (wid >> 1) << 4, wn = (wid & 1) << 6;
    int lr = lane >> 2, ka = lane & 3;
    int r = t >> 2, q = t & 3;
    int n0 = blockIdx.x * BM;
    int row = min(n0 + r, NN - 1);
    float rd = 1.f / fmaxf(g_deg[row], 1.f);

    float acc[8][4];
#pragma unroll
    for (int i = 0; i < 8; i++)
#pragma unroll
        for (int j = 0; j < 4; j++) acc[i][j] = 0.f;
#pragma unroll 1
    for (int c = 0; c < 8; c++) {
        __syncthreads();
        const float* p = (c < 4) ? (g_h + (ll)row * HH + c * 32)
                                 : (g_agg + (ll)row * HH + (c - 4) * 32);
        float sc = (c < 4) ? 1.f : rd;
        float4 v0 = *(const float4*)(p + q * 4);
        float4 v1 = *(const float4*)(p + 16 + q * 4);
        v0.x *= sc; v0.y *= sc; v0.z *= sc; v0.w *= sc;
        v1.x *= sc; v1.y *= sc; v1.z *= sc; v1.w *= sc;
        stage_Abf(Ah, Al, r, q, v0, v1);
        stage_Bpre(B1h, B1l, wu_h, wu_l, c * 16);
        __syncthreads();
        mma3_bf(Ah, Al, B1h, B1l, wm, wn, lr, ka, acc);
    }
    frag_relu_toCf(Cf, acc, bU, wm, wn, lr, ka);

    {
        float4 z = make_float4(0.f, 0.f, 0.f, 0.f);
#pragma unroll
        for (int i = 0; i < 8; i++) {
            int f = t + i * TPB;
            int rr = n0 + (f >> 5);
            if (rr < NN)
                *(float4*)(g_agg + (ll)rr * HH + ((f & 31) << 2)) = z;
        }
    }

#pragma unroll
    for (int i = 0; i < 8; i++)
#pragma unroll
        for (int j = 0; j < 4; j++) acc[i][j] = 0.f;
#pragma unroll 1
    for (int kc = 0; kc < 4; kc++) {
        __syncthreads();
        stage_Abf_fromCf(Ah, Al, Cf, kc);
        stage_Bpre(B1h, B1l, wn_h, wn_l, kc * 16);
        __syncthreads();
        mma3_bf(Ah, Al, B1h, B1l, wm, wn, lr, ka, acc);
    }
    __syncthreads();
    frag_relu_toCf(Cf, acc, bn, wm, wn, lr, ka);
    __syncthreads();
#pragma unroll
    for (int i = 0; i < 8; i++) {
        int f = t + i * TPB;
        int rr = f >> 5, c4 = (f & 31) << 2;
        int gr = n0 + rr;
        if (gr < NN)
            *(float4*)(g_h + (ll)gr * HH + c4) = *(const float4*)(Cf + rr * LDA + c4);
    }

    if (has_next)
        p_passes(Ah, Al, B1h, B1l, B2h, B2l, Cf, layer + 1, n0, wm, wn, lr, ka);
}

// ---------------- global mean pool ----------------
__global__ void k_pool(const int* __restrict__ bvec) {
    int t = blockIdx.x * blockDim.x + threadIdx.x;
    int c4 = (t & 31) << 2;
    int nb = (t >> 5) * 16;
    if (nb >= NN) return;
    int end = min(nb + 16, NN);
    int g = bvec[nb];
    float4 s = make_float4(0.f, 0.f, 0.f, 0.f);
    float cnt = 0.f;
    for (int n = nb; n < end; n++) {
        int gn = bvec[n];
        if (gn != g) {
            atomicAdd((float4*)(g_pool + g * HH + c4), s);
            if (c4 == 0) atomicAdd(&g_cnt[g], cnt);
            s = make_float4(0.f, 0.f, 0.f, 0.f);
            cnt = 0.f;
            g = gn;
        }
        float4 hv = *(const float4*)(g_h + (ll)n * HH + c4);
        s.x += hv.x; s.y += hv.y; s.z += hv.z; s.w += hv.w;
        cnt += 1.f;
    }
    atomicAdd((float4*)(g_pool + g * HH + c4), s);
    if (c4 == 0) atomicAdd(&g_cnt[g], cnt);
}

__global__ void k_head(const float* __restrict__ Wh, const float* __restrict__ bh,
                       float* __restrict__ out) {
    int g = threadIdx.x;
    float rc = 1.f / fmaxf(g_cnt[g], 1.f);
    float acc = bh[0];
#pragma unroll
    for (int k = 0; k < HH; k++)
        acc += g_pool[g * HH + k] * rc * Wh[k];
    out[g] = acc;
}

// ---------------- launch ----------------
extern "C" void kernel_launch(void* const* d_in, const int* in_sizes, int n_in,
                              void* d_out, int out_size) {
    const float* x    = (const float*)d_in[0];
    const int*   ei   = (const int*)d_in[1];
    const float* ea   = (const float*)d_in[2];
    const int*   bvec = (const int*)d_in[3];
    const float* Wn0  = (const float*)d_in[4];
    const float* bn0  = (const float*)d_in[5];
    const float* We0  = (const float*)d_in[6];
    const float* be0  = (const float*)d_in[7];
    const float* WM   = (const float*)d_in[8];
    const float* bM   = (const float*)d_in[9];
    const float* WU   = (const float*)d_in[10];
    const float* bU   = (const float*)d_in[11];
    const float* Wn   = (const float*)d_in[12];
    const float* bn   = (const float*)d_in[13];
    const float* We   = (const float*)d_in[14];
    const float* be   = (const float*)d_in[15];
    const float* Wh   = (const float*)d_in[16];
    const float* bh   = (const float*)d_in[17];
    float* out = (float*)d_out;

    const int* src = ei;
    const int* dst = ei + EE;

    static int attr_done = 0;
    if (!attr_done) {
        cudaFuncSetAttribute(k_edge_tf32, cudaFuncAttributeMaxDynamicSharedMemorySize,
                             EDGE_SMEM);
        cudaFuncSetAttribute(k_enc_fused, cudaFuncAttributeMaxDynamicSharedMemorySize,
                             NODE_SMEM);
        cudaFuncSetAttribute(k_update_fused, cudaFuncAttributeMaxDynamicSharedMemorySize,
                             NODE_SMEM);
        attr_done = 1;
    }

    int prep_threads = 3 * 40960 + 2 * 3 * 16384 + 16 * HH + NN;
    k_prep<<<(prep_threads + 255) / 256, 256>>>(WM, WU, Wn, We, We0);

    k_deg<<<(EE + 255) / 256, 256>>>(dst);

    int nblk = (NN + BM - 1) / BM;
    k_enc_fused<<<nblk, TPB, NODE_SMEM>>>(x, Wn0, bn0);

    for (int l = 0; l < 3; l++) {
        k_edge_tf32<<<EE / EBM, ETPB, EDGE_SMEM>>>(src, dst, l, bM + l * HH,
                                                   be + l * HH, ea, be0,
                                                   l < 2 ? 1 : 0);
        k_update_fused<<<nblk, TPB, NODE_SMEM>>>(l, bU + l * HH, bn + l * HH,
                                                 l < 2 ? 1 : 0);
    }

    int pool_threads = ((NN + 15) / 16) * 32;
    k_pool<<<(pool_threads + 255) / 256, 256>>>(bvec);
    k_head<<<1, GG>>>(Wh, bh, out);
}